// round 14
// baseline (speedup 1.0000x reference)
#include <cuda_runtime.h>
#include <math.h>

#define NP   528
#define NPH  272        // padded half-width (cols 0..264 valid)
#define NIMG 24
#define NB   8
#define LPB  8          // lines per block
#define TPL  48         // threads per line team
#define BLKT (LPB*TPL)  // 384 threads per block
#define LSTR 528        // shared line stride (float2 units)
#define TWSZ 496        // FFT core never indexes tw above 480

// ---------------- scratch (static device globals; no runtime allocation) ----
__device__ float2 g_tw[NP];                          // e^{-2*pi*i*n/528}
__device__ float2 g_bufA[(size_t)NIMG*NP*NPH];       // ping  [img][row][col<265]
__device__ float2 g_bufB[(size_t)NIMG*NP*NPH];       // pong; front also reused as
                                                     // float band-blur [img][528][528]
__device__ float2 g_M[(size_t)NB*NP*NPH];            // collapsed wiener multiplier
__device__ float  g_wn[24*25];                       // normalized wiener filters
__device__ float  g_A[81];                           // filter autocorrelation 9x9
__device__ float  g_r0[NB*17];                       // psf row-proj autocorr
__device__ float  g_r1[NB*17];                       // psf col-proj autocorr
__device__ float  g_ad[4];                           // exp(alpha_d)
__device__ float  g_wt[4];                           // weights_d

// ---------------- helpers ----------------------------------------------------
__device__ __forceinline__ int sympad(int p) {
    return p < 8 ? 7 - p : (p < 520 ? p - 8 : 1031 - p);
}
__device__ __forceinline__ int m528(int x) {
    x %= NP; return x < 0 ? x + NP : x;
}
// unnormalized beta (caller multiplies by 1/r[0]); 0 exactly for 17<=i<=510
__device__ __forceinline__ float betaraw(int i, const float* r) {
    if (i < 17)  return r[i];
    if (i == 527) return r[0];
    if (i > 510) return r[527 - i];
    return 0.f;
}

// all table constants stored in e^{-i*theta} convention (cos, -sin); cmul<DIR>
// conjugates for the inverse transform.
template<int DIR>
__device__ __forceinline__ float2 cmul(float2 a, float2 w) {
    float wi = (DIR < 0) ? w.y : -w.y;
    return make_float2(a.x*w.x - a.y*wi, a.x*wi + a.y*w.x);
}
__device__ __forceinline__ float2 cadd(float2 a, float2 b){ return make_float2(a.x+b.x, a.y+b.y); }
__device__ __forceinline__ float2 csub(float2 a, float2 b){ return make_float2(a.x-b.x, a.y-b.y); }

// radix-4 in place: X_k = sum_n x_n W4^{nk}, W4 = e^{DIR*2*pi*i/4}
template<int DIR>
__device__ __forceinline__ void radix4(float2& a, float2& b, float2& c, float2& d) {
    float2 t0 = cadd(a,c), t1 = csub(a,c), t2 = cadd(b,d), t3 = csub(b,d);
    float2 mi = (DIR < 0) ? make_float2(t3.y, -t3.x) : make_float2(-t3.y, t3.x); // ∓ i*t3
    a = cadd(t0, t2);
    c = csub(t0, t2);
    b = cadd(t1, mi);
    d = csub(t1, mi);
}

#define W16_1 make_float2( 0.923879532511286756f, -0.382683432365089772f)
#define W16_2 make_float2( 0.707106781186547524f, -0.707106781186547524f)
#define W16_3 make_float2( 0.382683432365089772f, -0.923879532511286756f)
#define W16_4 make_float2( 0.f, -1.f)
#define W16_6 make_float2(-0.707106781186547524f, -0.707106781186547524f)
#define W16_9 make_float2(-0.923879532511286756f,  0.382683432365089772f)
#define W3_1  make_float2(-0.5f, -0.866025403784438647f)
#define W3_2  make_float2(-0.5f,  0.866025403784438647f)

// cos/sin(2*pi*m/11), m=1..5 (positive values; signs in the per-k rows)
#define C11_1 ( 0.841253532831181168f)
#define C11_2 ( 0.415415013001886426f)
#define C11_3 (-0.142314838273285140f)
#define C11_4 (-0.654860733945285064f)
#define C11_5 (-0.959492973614497389f)
#define S11_1 ( 0.540640817455597582f)
#define S11_2 ( 0.909631995354518371f)
#define S11_3 ( 0.989821441880932732f)
#define S11_4 ( 0.755749574354258283f)
#define S11_5 ( 0.281732556841429913f)

// ---------------- length-528 DFT, stages 16 (=4x4 register FFT) x 33 (=3x11) --
// TPL=48 threads/line, LPB lines per 384-thread block, block-wide __syncthreads
// (single HW barrier id). Fully IN-PLACE in sA: stage 1 owns its column;
// stage 2 (48 units, one per thread, 100% util) folds its 33 row inputs into
// registers, then a barrier separates reads from scatter writes.
// DIR=-1 fwd, +1 inv (unscaled). ALL 384 threads must call in lockstep; t<48.
template<int DIR>
__device__ void fft528(float2* sA, const float2* tw, int t) {
    __syncthreads();
    // ---- stage 1 (in place): one unit per n2 (t<33): 16-point register FFT
    //      over n1, inter-stage twiddle W528^{k1*n2}; write back to own column.
    if (t < 33) {
        int n2 = t;
        float2 q0[4], q1[4], q2[4], q3[4];
        #pragma unroll
        for (int n2p = 0; n2p < 4; n2p++) {
            float2 a = sA[ n2p     *33 + n2];
            float2 b = sA[(4+n2p)  *33 + n2];
            float2 c = sA[(8+n2p)  *33 + n2];
            float2 d = sA[(12+n2p) *33 + n2];
            radix4<DIR>(a, b, c, d);
            q0[n2p]=a; q1[n2p]=b; q2[n2p]=c; q3[n2p]=d;
        }
        float2 U[16];
        { float2 a=q0[0], b=q0[1], c=q0[2], d=q0[3];
          radix4<DIR>(a,b,c,d); U[0]=a; U[4]=b; U[8]=c; U[12]=d; }
        { float2 a=q1[0];
          float2 b=cmul<DIR>(q1[1], W16_1);
          float2 c=cmul<DIR>(q1[2], W16_2);
          float2 d=cmul<DIR>(q1[3], W16_3);
          radix4<DIR>(a,b,c,d); U[1]=a; U[5]=b; U[9]=c; U[13]=d; }
        { float2 a=q2[0];
          float2 b=cmul<DIR>(q2[1], W16_2);
          float2 c=cmul<DIR>(q2[2], W16_4);
          float2 d=cmul<DIR>(q2[3], W16_6);
          radix4<DIR>(a,b,c,d); U[2]=a; U[6]=b; U[10]=c; U[14]=d; }
        { float2 a=q3[0];
          float2 b=cmul<DIR>(q3[1], W16_3);
          float2 c=cmul<DIR>(q3[2], W16_6);
          float2 d=cmul<DIR>(q3[3], W16_9);
          radix4<DIR>(a,b,c,d); U[3]=a; U[7]=b; U[11]=c; U[15]=d; }
        #pragma unroll
        for (int m = 0; m < 16; m++)
            sA[m*33 + n2] = cmul<DIR>(U[m], tw[m*n2]);   // m*n2 <= 480
    }
    __syncthreads();
    // ---- stage 2: per k1 a 33-point DFT over n2, split 33 = 3 x 11.
    //      Phase A: load row k1 + radix-3 fold + twiddle into v[11] (regs).
    //      Barrier. Phase B: 11-pt conj-pair DFT, scatter-write into sA.
    {
        int k1 = t & 15, k1p = t >> 4;   // t < 48 -> k1p in {0,1,2}
        float2 v[11];
        {
            float2 w3a, w3b;
            if (k1p == 1)      { w3a = W3_1; w3b = W3_2; }
            else if (k1p == 2) { w3a = W3_2; w3b = W3_1; }
            else               { w3a = make_float2(1.f,0.f); w3b = w3a; }
            const float2* y = sA + k1*33;
            int tstep = 16 * k1p;
            #pragma unroll
            for (int q = 0; q < 11; q++) {
                float2 a = y[q], b = y[11+q], c = y[22+q];
                float2 uu = cadd(a, cadd(cmul<DIR>(b, w3a), cmul<DIR>(c, w3b)));
                v[q] = cmul<DIR>(uu, tw[tstep*q]);       // <= 320
            }
        }
        __syncthreads();
        {
            float2 v0  = v[0];
            float2 ss1 = cadd(v[1], v[10]), dd1 = csub(v[1], v[10]);
            float2 ss2 = cadd(v[2], v[9]),  dd2 = csub(v[2], v[9]);
            float2 ss3 = cadd(v[3], v[8]),  dd3 = csub(v[3], v[8]);
            float2 ss4 = cadd(v[4], v[7]),  dd4 = csub(v[4], v[7]);
            float2 ss5 = cadd(v[5], v[6]),  dd5 = csub(v[5], v[6]);
            sA[k1 + 16*k1p] = make_float2(
                v0.x + ss1.x + ss2.x + ss3.x + ss4.x + ss5.x,
                v0.y + ss1.y + ss2.y + ss3.y + ss4.y + ss5.y);
            #define OUTIDX(kk) (k1 + 16*(k1p + 3*(kk)))
            #define DFT11P(kk, cA,cB,cC,cD,cE, sP,sQ,sR,sS,sT) { \
                float Ax = fmaf(cA,ss1.x, fmaf(cB,ss2.x, fmaf(cC,ss3.x, fmaf(cD,ss4.x, fmaf(cE,ss5.x, v0.x))))); \
                float Ay = fmaf(cA,ss1.y, fmaf(cB,ss2.y, fmaf(cC,ss3.y, fmaf(cD,ss4.y, fmaf(cE,ss5.y, v0.y))))); \
                float Sx = fmaf(sP,dd1.x, fmaf(sQ,dd2.x, fmaf(sR,dd3.x, fmaf(sS,dd4.x, sT*dd5.x)))); \
                float Sy = fmaf(sP,dd1.y, fmaf(sQ,dd2.y, fmaf(sR,dd3.y, fmaf(sS,dd4.y, sT*dd5.y)))); \
                if (DIR < 0) { \
                    sA[OUTIDX(kk)]      = make_float2(Ax + Sy, Ay - Sx); \
                    sA[OUTIDX(11-(kk))] = make_float2(Ax - Sy, Ay + Sx); \
                } else { \
                    sA[OUTIDX(kk)]      = make_float2(Ax - Sy, Ay + Sx); \
                    sA[OUTIDX(11-(kk))] = make_float2(Ax + Sy, Ay - Sx); \
                } }
            DFT11P(1, C11_1,C11_2,C11_3,C11_4,C11_5,  S11_1, S11_2, S11_3, S11_4, S11_5)
            DFT11P(2, C11_2,C11_4,C11_5,C11_3,C11_1,  S11_2, S11_4,-S11_5,-S11_3,-S11_1)
            DFT11P(3, C11_3,C11_5,C11_2,C11_1,C11_4,  S11_3,-S11_5,-S11_2, S11_1, S11_4)
            DFT11P(4, C11_4,C11_3,C11_1,C11_5,C11_2,  S11_4,-S11_3, S11_1, S11_5,-S11_2)
            DFT11P(5, C11_5,C11_1,C11_4,C11_2,C11_3,  S11_5,-S11_1, S11_4,-S11_2, S11_3)
            #undef DFT11P
            #undef OUTIDX
        }
    }
    __syncthreads();
}

// ---------------- prep kernel --------------------------------------------------
__global__ void k_prep(const float* wcw, const float* wscale, const float* alpha,
                       const float* wts, const float* blurK) {
    int t = threadIdx.x;
    if (t < NP) {
        double a = -6.28318530717958647692528676655900577 * (double)t / (double)NP;
        g_tw[t] = make_float2((float)cos(a), (float)sin(a));
    }
    if (t < 24) {
        float m = 0.f;
        for (int i = 0; i < 25; i++) m += wcw[t*25 + i];
        m *= (1.f/25.f);
        float ss = 0.f;
        for (int i = 0; i < 25; i++) { float d = wcw[t*25+i] - m; ss += d*d; }
        float s = wscale[t] / sqrtf(ss);
        for (int i = 0; i < 25; i++) g_wn[t*25 + i] = (wcw[t*25+i] - m) * s;
    }
    if (t >= 96 && t < 104) {
        int b = t - 96;
        float p0[17], p1[17];
        for (int u = 0; u < 17; u++) { p0[u] = 0.f; p1[u] = 0.f; }
        for (int u = 0; u < 17; u++)
            for (int v = 0; v < 17; v++) {
                float pv = blurK[b*289 + u*17 + v];
                p0[u] += pv; p1[v] += pv;
            }
        for (int n = 0; n < 17; n++) {
            float a0 = 0.f, a1 = 0.f;
            for (int m2 = 0; m2 + n < 17; m2++) {
                a0 += p0[m2] * p0[m2+n];
                a1 += p1[m2] * p1[m2+n];
            }
            g_r0[b*17 + n] = a0;
            g_r1[b*17 + n] = a1;
        }
    }
    if (t == 511) {
        for (int d = 0; d < 4; d++) { g_ad[d] = expf(alpha[d]); g_wt[d] = wts[d]; }
    }
    __syncthreads();
    if (t < 81) {
        int du = t/9 - 4, dv = t%9 - 4;
        float acc = 0.f;
        for (int f = 0; f < 24; f++)
            for (int u = 0; u < 5; u++)
                for (int v = 0; v < 5; v++) {
                    int uu = u + du, vv = v + dv;
                    if (uu >= 0 && uu < 5 && vv >= 0 && vv < 5)
                        acc += g_wn[f*25 + uu*5 + vv] * g_wn[f*25 + u*5 + v];
                }
        g_A[t] = acc;
    }
}

// ---------------- fused spectrum kernel: rv + Greg + M  ----------------------
// grid (33, NB), 272 threads; 16 w1 rows per block.
__global__ void k_spec(const float* blurK) {
    __shared__ float psf[289];
    __shared__ float A[81];
    __shared__ float twc[NP];
    int bx = blockIdx.x;     // 0..32 (w1 chunk)
    int b  = blockIdx.y;
    int w2 = threadIdx.x;    // 272 threads
    for (int i = w2; i < 289; i += 272) psf[i] = blurK[b*289 + i];
    if (w2 < 81) A[w2] = g_A[w2];
    for (int i = w2; i < NP; i += 272) twc[i] = g_tw[i].x;
    __syncthreads();
    if (w2 >= 265) return;
    float2 rv[17];
    {
        float2 wv[17];
        int ix = m528(-8 * w2);
        #pragma unroll
        for (int v = 0; v < 17; v++) {
            wv[v] = g_tw[ix];
            ix += w2; if (ix >= NP) ix -= NP;
        }
        #pragma unroll
        for (int u = 0; u < 17; u++) {
            float re = 0.f, im = 0.f;
            #pragma unroll
            for (int v = 0; v < 17; v++) {
                float p = psf[u*17 + v];
                re += p * wv[v].x; im += p * wv[v].y;
            }
            rv[u] = make_float2(re, im);
        }
    }
    for (int w1c = 0; w1c < 16; w1c++) {
        int w1 = bx*16 + w1c;
        float gacc = 0.f;
        {
            int ib = m528(-4 * (w1 + w2));
            #pragma unroll
            for (int du = 0; du < 4; du++) {
                int ix = ib;
                #pragma unroll
                for (int dv = 0; dv < 9; dv++) {
                    gacc += A[du*9 + dv] * twc[ix];
                    ix += w2; if (ix >= NP) ix -= NP;
                }
                ib += w1; if (ib >= NP) ib -= NP;
            }
            int ix = ib;
            #pragma unroll
            for (int dv = 0; dv < 4; dv++) {
                gacc += A[36 + dv] * twc[ix];
                ix += w2; if (ix >= NP) ix -= NP;
            }
        }
        float gg = fmaf(2.f, gacc, A[40]);
        float kr = 0.f, ki = 0.f;
        int ix = m528(-8 * w1);
        #pragma unroll
        for (int u = 0; u < 17; u++) {
            float2 w = g_tw[ix];
            ix += w1; if (ix >= NP) ix -= NP;
            kr += w.x*rv[u].x - w.y*rv[u].y;
            ki += w.x*rv[u].y + w.y*rv[u].x;
        }
        float s2 = kr*kr + ki*ki;
        float acc = 0.f;
        #pragma unroll
        for (int d = 0; d < 4; d++) acc += __fdividef(g_wt[d], fmaf(g_ad[d], gg, s2));
        g_M[(size_t)b*NP*NPH + (size_t)w1*NPH + w2] = make_float2(kr*acc, -ki*acc);
    }
}

// ---------------- band blur (spatial 17x17 circular conv, band only) ---------
__global__ void __launch_bounds__(64) k_band(const float* image, const float* blurK) {
    __shared__ float psf_s[289];
    __shared__ float tile[2640];
    int t = threadIdx.x;
    int side = blockIdx.y;       // 0,1
    int img = blockIdx.z;        // 0..23
    int b = img / 3;
    for (int i = t; i < 289; i += 64) psf_s[i] = blurK[b*289 + i];
    const float* im = image + (size_t)img*512*512;
    float* bb = (float*)g_bufB + (size_t)img*528*528;
    if (blockIdx.x < 9) {
        int c0 = blockIdx.x * 64;
        int base = side ? 511 : 0;
        for (int e = t; e < 33*80; e += 64) {
            int i = e / 80, j = e % 80;
            int rr = (base - 8 + i + 528) % 528;
            int cc = (c0 - 8 + j + 528) % 528;
            tile[i*80 + j] = im[sympad(rr)*512 + sympad(cc)];
        }
        __syncthreads();
        int c = c0 + t;
        if (c >= 528) return;
        float col[33];
        float acc[17];
        #pragma unroll
        for (int r = 0; r < 17; r++) acc[r] = 0.f;
        for (int v = 0; v < 17; v++) {
            #pragma unroll
            for (int i = 0; i < 33; i++) col[i] = tile[i*80 + t + 16 - v];
            #pragma unroll
            for (int u = 0; u < 17; u++) {
                float s = psf_s[u*17 + v];
                #pragma unroll
                for (int r = 0; r < 17; r++)
                    acc[r] = fmaf(s, col[r - u + 16], acc[r]);
            }
        }
        #pragma unroll
        for (int r = 0; r < 17; r++) bb[(size_t)(base + r)*528 + c] = acc[r];
    } else {
        int rg = blockIdx.x - 9;     // 0..7
        int r0 = 17 + rg*64;
        int basec = side ? 511 : 0;
        for (int e = t; e < 80*33; e += 64) {
            int i = e / 33, j = e % 33;
            int rr = (r0 - 8 + i) % 528;
            int cc = (basec - 8 + j + 528) % 528;
            tile[i*33 + j] = im[sympad(rr)*512 + sympad(cc)];
        }
        __syncthreads();
        int r = r0 + t;
        if (r > 510) return;
        float rowv[33];
        float acc[17];
        #pragma unroll
        for (int c = 0; c < 17; c++) acc[c] = 0.f;
        for (int u = 0; u < 17; u++) {
            #pragma unroll
            for (int j = 0; j < 33; j++) rowv[j] = tile[(t + 16 - u)*33 + j];
            #pragma unroll
            for (int v = 0; v < 17; v++) {
                float s = psf_s[u*17 + v];
                #pragma unroll
                for (int c = 0; c < 17; c++)
                    acc[c] = fmaf(s, rowv[c - v + 16], acc[c]);
            }
        }
        #pragma unroll
        for (int c = 0; c < 17; c++) bb[(size_t)r*528 + basec + c] = acc[c];
    }
}

// ---------------- big passes (8 lines x 48 threads per 384-thread block) ------
// P1E: symmetric-pad + inline edgetaper mix (blur from band buffer), pack two
// real rows, one forward FFT, Hermitian unpack -> bufA.
__global__ void __launch_bounds__(BLKT, 5) k_p1e(const float* image) {
    __shared__ float2 tw[TWSZ];
    __shared__ float2 sA[LPB][LSTR];
    int tid = threadIdx.x;
    int team = tid / TPL, t = tid - team*TPL;
    for (int i = tid; i < TWSZ; i += BLKT) tw[i] = g_tw[i];
    int line = blockIdx.x*LPB + team;         // pair index
    int img = line / 264, q = line % 264;
    int r1 = 2*q, r2 = 2*q + 1;
    int b = img / 3;
    const float* ar0 = g_r0 + b*17;
    const float* ar1 = g_r1 + b*17;
    float inv0 = 1.f / ar0[0];
    float inv1 = 1.f / ar1[0];
    float b01 = betaraw(r1, ar0) * inv0;
    float b02 = betaraw(r2, ar0) * inv0;
    const float* src1 = image + ((size_t)img*512 + sympad(r1))*512;
    const float* src2 = image + ((size_t)img*512 + sympad(r2))*512;
    const float* bb1 = (const float*)g_bufB + ((size_t)img*528 + r1)*528;
    const float* bb2 = (const float*)g_bufB + ((size_t)img*528 + r2)*528;
    for (int j = t; j < NP; j += TPL) {
        float b1j = betaraw(j, ar1) * inv1;
        float a1 = (1.f - b01) * (1.f - b1j);
        float a2 = (1.f - b02) * (1.f - b1j);
        int sj = sympad(j);
        float x1 = src1[sj], x2 = src2[sj];
        if (a1 != 1.f) x1 = a1 * x1 + (1.f - a1) * bb1[j];
        if (a2 != 1.f) x2 = a2 * x2 + (1.f - a2) * bb2[j];
        sA[team][j] = make_float2(x1, x2);
    }
    fft528<-1>(sA[team], tw, t);
    float2* d1 = g_bufA + (size_t)img*NP*NPH + (size_t)r1*NPH;
    float2* d2 = g_bufA + (size_t)img*NP*NPH + (size_t)r2*NPH;
    for (int k = t; k < 265; k += TPL) {
        float2 Zk = sA[team][k];
        float2 Zm = sA[team][(NP - k) % NP];
        d1[k] = make_float2(0.5f*(Zk.x + Zm.x), 0.5f*(Zk.y - Zm.y));
        d2[k] = make_float2(0.5f*(Zk.y + Zm.y), 0.5f*(Zm.x - Zk.x));
    }
}

// Column pass over half-width columns: col FFT, multiply spectrum M,
// col IFFT (x 1/528). bufA -> bufB. float4 global I/O, 8 cols per block.
__global__ void __launch_bounds__(BLKT, 5) k_colpass() {
    __shared__ float2 tw[TWSZ];
    __shared__ float2 sA[LPB][LSTR];
    int tid = threadIdx.x;
    int team = tid / TPL, t = tid - team*TPL;
    for (int i = tid; i < TWSZ; i += BLKT) tw[i] = g_tw[i];
    int img = blockIdx.y;
    int c0  = blockIdx.x * LPB;   // cols 265..271 compute garbage (never read)
    int b   = img / 3;
    const float4* in4  = (const float4*)(g_bufA + (size_t)img * NP * NPH);
    float4*       out4 = (float4*)(g_bufB + (size_t)img * NP * NPH);
    const float4* spec4 = (const float4*)(g_M + (size_t)b * NP * NPH);
    for (int e = tid; e < NP*4; e += BLKT) {
        int r = e >> 2, p = e & 3;
        float4 v = in4[(r*NPH + c0)/2 + p];
        sA[2*p  ][r] = make_float2(v.x, v.y);
        sA[2*p+1][r] = make_float2(v.z, v.w);
    }
    fft528<-1>(sA[team], tw, t);
    for (int e = tid; e < NP*4; e += BLKT) {
        int r = e >> 2, p = e & 3;
        float4 s = spec4[(r*NPH + c0)/2 + p];
        float2 v0 = sA[2*p][r], v1 = sA[2*p+1][r];
        sA[2*p  ][r] = make_float2(v0.x*s.x - v0.y*s.y, v0.x*s.y + v0.y*s.x);
        sA[2*p+1][r] = make_float2(v1.x*s.z - v1.y*s.w, v1.x*s.w + v1.y*s.z);
    }
    fft528<1>(sA[team], tw, t);
    const float inv = 1.f / NP;
    for (int e = tid; e < NP*4; e += BLKT) {
        int r = e >> 2, p = e & 3;
        float2 v0 = sA[2*p][r], v1 = sA[2*p+1][r];
        out4[(r*NPH + c0)/2 + p] = make_float4(v0.x*inv, v0.y*inv, v1.x*inv, v1.y*inv);
    }
}

// P5: two Hermitian half-rows -> packed IFFT, crop, write both output rows.
__global__ void __launch_bounds__(BLKT, 5) k_p5(float* outp) {
    __shared__ float2 tw[TWSZ];
    __shared__ float2 sA[LPB][LSTR];
    int tid = threadIdx.x;
    int team = tid / TPL, t = tid - team*TPL;
    for (int i = tid; i < TWSZ; i += BLKT) tw[i] = g_tw[i];
    int line = blockIdx.x*LPB + team;
    int img = line / 256, q = line % 256;
    int o1 = 2*q, o2 = 2*q + 1;
    int r1 = o1 + 8, r2 = o2 + 8;
    const float2* i1 = g_bufB + (size_t)img*NP*NPH + (size_t)r1*NPH;
    const float2* i2 = g_bufB + (size_t)img*NP*NPH + (size_t)r2*NPH;
    for (int m = t; m < 265; m += TPL) {
        float2 B1 = i1[m], B2 = i2[m];
        sA[team][m] = make_float2(B1.x - B2.y, B1.y + B2.x);
        if (m >= 1 && m <= 263)
            sA[team][NP - m] = make_float2(B1.x + B2.y, B2.x - B1.y);
    }
    fft528<1>(sA[team], tw, t);
    const float inv = 1.f / NP;
    float* d1 = outp + ((size_t)img*512 + o1)*512;
    float* d2 = outp + ((size_t)img*512 + o2)*512;
    for (int j = 8 + t; j < 520; j += TPL) {
        float2 z = sA[team][j];
        d1[j - 8] = z.x * inv;
        d2[j - 8] = z.y * inv;
    }
}

// ---------------- launch ------------------------------------------------------
extern "C" void kernel_launch(void* const* d_in, const int* in_sizes, int n_in,
                              void* d_out, int out_size) {
    const float* image  = (const float*)d_in[0];
    const float* blurK  = (const float*)d_in[1];
    // d_in[2] = stdn (unused by the reference forward pass)
    const float* wcw    = (const float*)d_in[3];
    const float* wscale = (const float*)d_in[4];
    const float* alpha  = (const float*)d_in[5];
    const float* wts    = (const float*)d_in[6];
    float* outp = (float*)d_out;

    k_band<<<dim3(17, 2, NIMG), 64>>>(image, blurK);
    k_prep<<<1, NP>>>(wcw, wscale, alpha, wts, blurK);
    k_spec<<<dim3(33, NB), NPH>>>(blurK);

    k_p1e<<<(NIMG*264)/LPB, BLKT>>>(image);
    k_colpass<<<dim3(34, NIMG), BLKT>>>();
    k_p5<<<(NIMG*256)/LPB, BLKT>>>(outp);
}

// round 15
// speedup vs baseline: 1.0202x; 1.0202x over previous
#include <cuda_runtime.h>
#include <math.h>

#define NP   528
#define NPH  272        // padded half-width (cols 0..264 valid)
#define NIMG 24
#define NB   8
#define LPB  4
#define LSTR 528        // shared line stride (float2 units)
#define TWSZ 496        // FFT core never indexes tw above 480

// ---------------- scratch (static device globals; no runtime allocation) ----
__device__ float2 g_tw[NP];                          // e^{-2*pi*i*n/528}
__device__ float2 g_bufA[(size_t)NIMG*NP*NPH];       // ping  [img][row][col<265]
__device__ float2 g_bufB[(size_t)NIMG*NP*NPH];       // pong; front also reused as
                                                     // float band-blur [img][528][528]
__device__ float2 g_M[(size_t)NB*NP*NPH];            // collapsed wiener multiplier
__device__ float  g_wn[24*25];                       // normalized wiener filters
__device__ float  g_A[81];                           // filter autocorrelation 9x9
__device__ float  g_r0[NB*17];                       // psf row-proj autocorr
__device__ float  g_r1[NB*17];                       // psf col-proj autocorr
__device__ float  g_ad[4];                           // exp(alpha_d)
__device__ float  g_wt[4];                           // weights_d

// ---------------- helpers ----------------------------------------------------
__device__ __forceinline__ int sympad(int p) {
    return p < 8 ? 7 - p : (p < 520 ? p - 8 : 1031 - p);
}
__device__ __forceinline__ int m528(int x) {
    x %= NP; return x < 0 ? x + NP : x;
}
// unnormalized beta (caller multiplies by 1/r[0]); 0 exactly for 17<=i<=510
__device__ __forceinline__ float betaraw(int i, const float* r) {
    if (i < 17)  return r[i];
    if (i == 527) return r[0];
    if (i > 510) return r[527 - i];
    return 0.f;
}

// all table constants stored in e^{-i*theta} convention (cos, -sin); cmul<DIR>
// conjugates for the inverse transform.
template<int DIR>
__device__ __forceinline__ float2 cmul(float2 a, float2 w) {
    float wi = (DIR < 0) ? w.y : -w.y;
    return make_float2(a.x*w.x - a.y*wi, a.x*wi + a.y*w.x);
}
__device__ __forceinline__ float2 cadd(float2 a, float2 b){ return make_float2(a.x+b.x, a.y+b.y); }
__device__ __forceinline__ float2 csub(float2 a, float2 b){ return make_float2(a.x-b.x, a.y-b.y); }

// radix-4 in place: X_k = sum_n x_n W4^{nk}, W4 = e^{DIR*2*pi*i/4}
template<int DIR>
__device__ __forceinline__ void radix4(float2& a, float2& b, float2& c, float2& d) {
    float2 t0 = cadd(a,c), t1 = csub(a,c), t2 = cadd(b,d), t3 = csub(b,d);
    float2 mi = (DIR < 0) ? make_float2(t3.y, -t3.x) : make_float2(-t3.y, t3.x); // ∓ i*t3
    a = cadd(t0, t2);
    c = csub(t0, t2);
    b = cadd(t1, mi);
    d = csub(t1, mi);
}

#define W16_1 make_float2( 0.923879532511286756f, -0.382683432365089772f)
#define W16_2 make_float2( 0.707106781186547524f, -0.707106781186547524f)
#define W16_3 make_float2( 0.382683432365089772f, -0.923879532511286756f)
#define W16_4 make_float2( 0.f, -1.f)
#define W16_6 make_float2(-0.707106781186547524f, -0.707106781186547524f)
#define W16_9 make_float2(-0.923879532511286756f,  0.382683432365089772f)
#define W3_1  make_float2(-0.5f, -0.866025403784438647f)
#define W3_2  make_float2(-0.5f,  0.866025403784438647f)

// cos/sin(2*pi*m/11), m=1..5 (positive values; signs in the per-k rows)
#define C11_1 ( 0.841253532831181168f)
#define C11_2 ( 0.415415013001886426f)
#define C11_3 (-0.142314838273285140f)
#define C11_4 (-0.654860733945285064f)
#define C11_5 (-0.959492973614497389f)
#define S11_1 ( 0.540640817455597582f)
#define S11_2 ( 0.909631995354518371f)
#define S11_3 ( 0.989821441880932732f)
#define S11_4 ( 0.755749574354258283f)
#define S11_5 ( 0.281732556841429913f)

// ---------------- length-528 DFT, stages 16 (=4x4 register FFT) x 33 (=3x11) --
// 64 threads/line (warp-aligned teams), LPB lines per 256-thread block,
// block-wide __syncthreads (single HW barrier id). Fully IN-PLACE in sA:
// stage 1 owns its column; stage 2 folds its 33 row inputs into registers,
// then a barrier separates reads from scatter writes. DIR=-1 fwd, +1 inv.
// ALL 256 threads of the block must call in lockstep.
template<int DIR>
__device__ void fft528(float2* sA, const float2* tw, int t) {
    __syncthreads();
    // ---- stage 1 (in place): one unit per n2 (t<33): 16-point register FFT
    //      over n1, inter-stage twiddle W528^{k1*n2}; write back to own column.
    if (t < 33) {
        int n2 = t;
        float2 q0[4], q1[4], q2[4], q3[4];
        #pragma unroll
        for (int n2p = 0; n2p < 4; n2p++) {
            float2 a = sA[ n2p     *33 + n2];
            float2 b = sA[(4+n2p)  *33 + n2];
            float2 c = sA[(8+n2p)  *33 + n2];
            float2 d = sA[(12+n2p) *33 + n2];
            radix4<DIR>(a, b, c, d);
            q0[n2p]=a; q1[n2p]=b; q2[n2p]=c; q3[n2p]=d;
        }
        float2 U[16];
        { float2 a=q0[0], b=q0[1], c=q0[2], d=q0[3];
          radix4<DIR>(a,b,c,d); U[0]=a; U[4]=b; U[8]=c; U[12]=d; }
        { float2 a=q1[0];
          float2 b=cmul<DIR>(q1[1], W16_1);
          float2 c=cmul<DIR>(q1[2], W16_2);
          float2 d=cmul<DIR>(q1[3], W16_3);
          radix4<DIR>(a,b,c,d); U[1]=a; U[5]=b; U[9]=c; U[13]=d; }
        { float2 a=q2[0];
          float2 b=cmul<DIR>(q2[1], W16_2);
          float2 c=cmul<DIR>(q2[2], W16_4);
          float2 d=cmul<DIR>(q2[3], W16_6);
          radix4<DIR>(a,b,c,d); U[2]=a; U[6]=b; U[10]=c; U[14]=d; }
        { float2 a=q3[0];
          float2 b=cmul<DIR>(q3[1], W16_3);
          float2 c=cmul<DIR>(q3[2], W16_6);
          float2 d=cmul<DIR>(q3[3], W16_9);
          radix4<DIR>(a,b,c,d); U[3]=a; U[7]=b; U[11]=c; U[15]=d; }
        #pragma unroll
        for (int m = 0; m < 16; m++)
            sA[m*33 + n2] = cmul<DIR>(U[m], tw[m*n2]);   // m*n2 <= 480
    }
    __syncthreads();
    // ---- stage 2: per k1 a 33-point DFT over n2, split 33 = 3 x 11.
    //      Phase A: load row k1 + radix-3 fold + twiddle into v[11] (regs).
    //      Barrier. Phase B: 11-pt conj-pair DFT, scatter-write into sA.
    {
        int k1 = t & 15, k1p = t >> 4;
        bool act = (k1p < 3);
        float2 v[11];
        if (act) {
            float2 w3a, w3b;
            if (k1p == 1)      { w3a = W3_1; w3b = W3_2; }
            else if (k1p == 2) { w3a = W3_2; w3b = W3_1; }
            else               { w3a = make_float2(1.f,0.f); w3b = w3a; }
            const float2* y = sA + k1*33;
            int tstep = 16 * k1p;
            #pragma unroll
            for (int q = 0; q < 11; q++) {
                float2 a = y[q], b = y[11+q], c = y[22+q];
                float2 uu = cadd(a, cadd(cmul<DIR>(b, w3a), cmul<DIR>(c, w3b)));
                v[q] = cmul<DIR>(uu, tw[tstep*q]);       // <= 320
            }
        }
        __syncthreads();
        if (act) {
            float2 v0  = v[0];
            float2 ss1 = cadd(v[1], v[10]), dd1 = csub(v[1], v[10]);
            float2 ss2 = cadd(v[2], v[9]),  dd2 = csub(v[2], v[9]);
            float2 ss3 = cadd(v[3], v[8]),  dd3 = csub(v[3], v[8]);
            float2 ss4 = cadd(v[4], v[7]),  dd4 = csub(v[4], v[7]);
            float2 ss5 = cadd(v[5], v[6]),  dd5 = csub(v[5], v[6]);
            sA[k1 + 16*k1p] = make_float2(
                v0.x + ss1.x + ss2.x + ss3.x + ss4.x + ss5.x,
                v0.y + ss1.y + ss2.y + ss3.y + ss4.y + ss5.y);
            #define OUTIDX(kk) (k1 + 16*(k1p + 3*(kk)))
            #define DFT11P(kk, cA,cB,cC,cD,cE, sP,sQ,sR,sS,sT) { \
                float Ax = fmaf(cA,ss1.x, fmaf(cB,ss2.x, fmaf(cC,ss3.x, fmaf(cD,ss4.x, fmaf(cE,ss5.x, v0.x))))); \
                float Ay = fmaf(cA,ss1.y, fmaf(cB,ss2.y, fmaf(cC,ss3.y, fmaf(cD,ss4.y, fmaf(cE,ss5.y, v0.y))))); \
                float Sx = fmaf(sP,dd1.x, fmaf(sQ,dd2.x, fmaf(sR,dd3.x, fmaf(sS,dd4.x, sT*dd5.x)))); \
                float Sy = fmaf(sP,dd1.y, fmaf(sQ,dd2.y, fmaf(sR,dd3.y, fmaf(sS,dd4.y, sT*dd5.y)))); \
                if (DIR < 0) { \
                    sA[OUTIDX(kk)]      = make_float2(Ax + Sy, Ay - Sx); \
                    sA[OUTIDX(11-(kk))] = make_float2(Ax - Sy, Ay + Sx); \
                } else { \
                    sA[OUTIDX(kk)]      = make_float2(Ax - Sy, Ay + Sx); \
                    sA[OUTIDX(11-(kk))] = make_float2(Ax + Sy, Ay - Sx); \
                } }
            DFT11P(1, C11_1,C11_2,C11_3,C11_4,C11_5,  S11_1, S11_2, S11_3, S11_4, S11_5)
            DFT11P(2, C11_2,C11_4,C11_5,C11_3,C11_1,  S11_2, S11_4,-S11_5,-S11_3,-S11_1)
            DFT11P(3, C11_3,C11_5,C11_2,C11_1,C11_4,  S11_3,-S11_5,-S11_2, S11_1, S11_4)
            DFT11P(4, C11_4,C11_3,C11_1,C11_5,C11_2,  S11_4,-S11_3, S11_1, S11_5,-S11_2)
            DFT11P(5, C11_5,C11_1,C11_4,C11_2,C11_3,  S11_5,-S11_1, S11_4,-S11_2, S11_3)
            #undef DFT11P
            #undef OUTIDX
        }
    }
    __syncthreads();
}

// ---------------- prep kernel --------------------------------------------------
__global__ void k_prep(const float* wcw, const float* wscale, const float* alpha,
                       const float* wts, const float* blurK) {
    int t = threadIdx.x;
    if (t < NP) {
        double a = -6.28318530717958647692528676655900577 * (double)t / (double)NP;
        g_tw[t] = make_float2((float)cos(a), (float)sin(a));
    }
    if (t < 24) {
        float m = 0.f;
        for (int i = 0; i < 25; i++) m += wcw[t*25 + i];
        m *= (1.f/25.f);
        float ss = 0.f;
        for (int i = 0; i < 25; i++) { float d = wcw[t*25+i] - m; ss += d*d; }
        float s = wscale[t] / sqrtf(ss);
        for (int i = 0; i < 25; i++) g_wn[t*25 + i] = (wcw[t*25+i] - m) * s;
    }
    if (t >= 96 && t < 104) {
        int b = t - 96;
        float p0[17], p1[17];
        for (int u = 0; u < 17; u++) { p0[u] = 0.f; p1[u] = 0.f; }
        for (int u = 0; u < 17; u++)
            for (int v = 0; v < 17; v++) {
                float pv = blurK[b*289 + u*17 + v];
                p0[u] += pv; p1[v] += pv;
            }
        for (int n = 0; n < 17; n++) {
            float a0 = 0.f, a1 = 0.f;
            for (int m2 = 0; m2 + n < 17; m2++) {
                a0 += p0[m2] * p0[m2+n];
                a1 += p1[m2] * p1[m2+n];
            }
            g_r0[b*17 + n] = a0;
            g_r1[b*17 + n] = a1;
        }
    }
    if (t == 511) {
        for (int d = 0; d < 4; d++) { g_ad[d] = expf(alpha[d]); g_wt[d] = wts[d]; }
    }
    __syncthreads();
    if (t < 81) {
        int du = t/9 - 4, dv = t%9 - 4;
        float acc = 0.f;
        for (int f = 0; f < 24; f++)
            for (int u = 0; u < 5; u++)
                for (int v = 0; v < 5; v++) {
                    int uu = u + du, vv = v + dv;
                    if (uu >= 0 && uu < 5 && vv >= 0 && vv < 5)
                        acc += g_wn[f*25 + uu*5 + vv] * g_wn[f*25 + u*5 + v];
                }
        g_A[t] = acc;
    }
}

// ---------------- fused spectrum kernel: rv + Greg + M  ----------------------
// grid (33, NB), 272 threads; 16 w1 rows per block.
__global__ void k_spec(const float* blurK) {
    __shared__ float psf[289];
    __shared__ float A[81];
    __shared__ float twc[NP];
    int bx = blockIdx.x;     // 0..32 (w1 chunk)
    int b  = blockIdx.y;
    int w2 = threadIdx.x;    // 272 threads
    for (int i = w2; i < 289; i += 272) psf[i] = blurK[b*289 + i];
    if (w2 < 81) A[w2] = g_A[w2];
    for (int i = w2; i < NP; i += 272) twc[i] = g_tw[i].x;
    __syncthreads();
    if (w2 >= 265) return;
    float2 rv[17];
    {
        float2 wv[17];
        int ix = m528(-8 * w2);
        #pragma unroll
        for (int v = 0; v < 17; v++) {
            wv[v] = g_tw[ix];
            ix += w2; if (ix >= NP) ix -= NP;
        }
        #pragma unroll
        for (int u = 0; u < 17; u++) {
            float re = 0.f, im = 0.f;
            #pragma unroll
            for (int v = 0; v < 17; v++) {
                float p = psf[u*17 + v];
                re += p * wv[v].x; im += p * wv[v].y;
            }
            rv[u] = make_float2(re, im);
        }
    }
    for (int w1c = 0; w1c < 16; w1c++) {
        int w1 = bx*16 + w1c;
        float gacc = 0.f;
        {
            int ib = m528(-4 * (w1 + w2));
            #pragma unroll
            for (int du = 0; du < 4; du++) {
                int ix = ib;
                #pragma unroll
                for (int dv = 0; dv < 9; dv++) {
                    gacc += A[du*9 + dv] * twc[ix];
                    ix += w2; if (ix >= NP) ix -= NP;
                }
                ib += w1; if (ib >= NP) ib -= NP;
            }
            int ix = ib;
            #pragma unroll
            for (int dv = 0; dv < 4; dv++) {
                gacc += A[36 + dv] * twc[ix];
                ix += w2; if (ix >= NP) ix -= NP;
            }
        }
        float gg = fmaf(2.f, gacc, A[40]);
        float kr = 0.f, ki = 0.f;
        int ix = m528(-8 * w1);
        #pragma unroll
        for (int u = 0; u < 17; u++) {
            float2 w = g_tw[ix];
            ix += w1; if (ix >= NP) ix -= NP;
            kr += w.x*rv[u].x - w.y*rv[u].y;
            ki += w.x*rv[u].y + w.y*rv[u].x;
        }
        float s2 = kr*kr + ki*ki;
        float acc = 0.f;
        #pragma unroll
        for (int d = 0; d < 4; d++) acc += __fdividef(g_wt[d], fmaf(g_ad[d], gg, s2));
        g_M[(size_t)b*NP*NPH + (size_t)w1*NPH + w2] = make_float2(kr*acc, -ki*acc);
    }
}

// ---------------- band blur (spatial 17x17 circular conv, band only) ---------
__global__ void __launch_bounds__(64) k_band(const float* image, const float* blurK) {
    __shared__ float psf_s[289];
    __shared__ float tile[2640];
    int t = threadIdx.x;
    int side = blockIdx.y;       // 0,1
    int img = blockIdx.z;        // 0..23
    int b = img / 3;
    for (int i = t; i < 289; i += 64) psf_s[i] = blurK[b*289 + i];
    const float* im = image + (size_t)img*512*512;
    float* bb = (float*)g_bufB + (size_t)img*528*528;
    if (blockIdx.x < 9) {
        int c0 = blockIdx.x * 64;
        int base = side ? 511 : 0;
        for (int e = t; e < 33*80; e += 64) {
            int i = e / 80, j = e % 80;
            int rr = (base - 8 + i + 528) % 528;
            int cc = (c0 - 8 + j + 528) % 528;
            tile[i*80 + j] = im[sympad(rr)*512 + sympad(cc)];
        }
        __syncthreads();
        int c = c0 + t;
        if (c >= 528) return;
        float col[33];
        float acc[17];
        #pragma unroll
        for (int r = 0; r < 17; r++) acc[r] = 0.f;
        for (int v = 0; v < 17; v++) {
            #pragma unroll
            for (int i = 0; i < 33; i++) col[i] = tile[i*80 + t + 16 - v];
            #pragma unroll
            for (int u = 0; u < 17; u++) {
                float s = psf_s[u*17 + v];
                #pragma unroll
                for (int r = 0; r < 17; r++)
                    acc[r] = fmaf(s, col[r - u + 16], acc[r]);
            }
        }
        #pragma unroll
        for (int r = 0; r < 17; r++) bb[(size_t)(base + r)*528 + c] = acc[r];
    } else {
        int rg = blockIdx.x - 9;     // 0..7
        int r0 = 17 + rg*64;
        int basec = side ? 511 : 0;
        for (int e = t; e < 80*33; e += 64) {
            int i = e / 33, j = e % 33;
            int rr = (r0 - 8 + i) % 528;
            int cc = (basec - 8 + j + 528) % 528;
            tile[i*33 + j] = im[sympad(rr)*512 + sympad(cc)];
        }
        __syncthreads();
        int r = r0 + t;
        if (r > 510) return;
        float rowv[33];
        float acc[17];
        #pragma unroll
        for (int c = 0; c < 17; c++) acc[c] = 0.f;
        for (int u = 0; u < 17; u++) {
            #pragma unroll
            for (int j = 0; j < 33; j++) rowv[j] = tile[(t + 16 - u)*33 + j];
            #pragma unroll
            for (int v = 0; v < 17; v++) {
                float s = psf_s[u*17 + v];
                #pragma unroll
                for (int c = 0; c < 17; c++)
                    acc[c] = fmaf(s, rowv[c - v + 16], acc[c]);
            }
        }
        #pragma unroll
        for (int c = 0; c < 17; c++) bb[(size_t)r*528 + basec + c] = acc[c];
    }
}

// ---------------- big passes --------------------------------------------------
// P1E: symmetric-pad + inline edgetaper mix (blur from band buffer), pack two
// real rows, one forward FFT, Hermitian unpack -> bufA.
__global__ void __launch_bounds__(256, 8) k_p1e(const float* image) {
    __shared__ float2 tw[TWSZ];
    __shared__ float2 sA[LPB][LSTR];
    int tx = threadIdx.x, ty = threadIdx.y;
    int tid = ty*64 + tx;
    for (int i = tid; i < TWSZ; i += 256) tw[i] = g_tw[i];
    int line = blockIdx.x*LPB + ty;           // pair index
    int img = line / 264, q = line % 264;
    int r1 = 2*q, r2 = 2*q + 1;
    int b = img / 3;
    const float* ar0 = g_r0 + b*17;
    const float* ar1 = g_r1 + b*17;
    float inv0 = 1.f / ar0[0];
    float inv1 = 1.f / ar1[0];
    float b01 = betaraw(r1, ar0) * inv0;
    float b02 = betaraw(r2, ar0) * inv0;
    const float* src1 = image + ((size_t)img*512 + sympad(r1))*512;
    const float* src2 = image + ((size_t)img*512 + sympad(r2))*512;
    const float* bb1 = (const float*)g_bufB + ((size_t)img*528 + r1)*528;
    const float* bb2 = (const float*)g_bufB + ((size_t)img*528 + r2)*528;
    for (int j = tx; j < NP; j += 64) {
        float b1j = betaraw(j, ar1) * inv1;
        float a1 = (1.f - b01) * (1.f - b1j);
        float a2 = (1.f - b02) * (1.f - b1j);
        int sj = sympad(j);
        float x1 = src1[sj], x2 = src2[sj];
        if (a1 != 1.f) x1 = a1 * x1 + (1.f - a1) * bb1[j];
        if (a2 != 1.f) x2 = a2 * x2 + (1.f - a2) * bb2[j];
        sA[ty][j] = make_float2(x1, x2);
    }
    fft528<-1>(sA[ty], tw, tx);
    float2* d1 = g_bufA + (size_t)img*NP*NPH + (size_t)r1*NPH;
    float2* d2 = g_bufA + (size_t)img*NP*NPH + (size_t)r2*NPH;
    for (int k = tx; k < 265; k += 64) {
        float2 Zk = sA[ty][k];
        float2 Zm = sA[ty][(NP - k) % NP];
        d1[k] = make_float2(0.5f*(Zk.x + Zm.x), 0.5f*(Zk.y - Zm.y));
        d2[k] = make_float2(0.5f*(Zk.y + Zm.y), 0.5f*(Zm.x - Zk.x));
    }
}

// Column pass over half-width columns: col FFT, multiply spectrum M,
// col IFFT (x 1/528). bufA -> bufB. float4 global I/O.
__global__ void __launch_bounds__(256, 8) k_colpass() {
    __shared__ float2 tw[TWSZ];
    __shared__ float2 sA[LPB][LSTR];
    int tx = threadIdx.x, ty = threadIdx.y;
    int tid = ty*64 + tx;
    for (int i = tid; i < TWSZ; i += 256) tw[i] = g_tw[i];
    int img = blockIdx.y;
    int c0  = blockIdx.x * LPB;
    int b   = img / 3;
    const float4* in4  = (const float4*)(g_bufA + (size_t)img * NP * NPH);
    float4*       out4 = (float4*)(g_bufB + (size_t)img * NP * NPH);
    const float4* spec4 = (const float4*)(g_M + (size_t)b * NP * NPH);
    for (int e = tid; e < NP*2; e += 256) {
        int r = e >> 1, p = e & 1;
        float4 v = in4[(r*NPH + c0)/2 + p];
        sA[2*p  ][r] = make_float2(v.x, v.y);
        sA[2*p+1][r] = make_float2(v.z, v.w);
    }
    fft528<-1>(sA[ty], tw, tx);
    for (int e = tid; e < NP*2; e += 256) {
        int r = e >> 1, p = e & 1;
        float4 s = spec4[(r*NPH + c0)/2 + p];
        float2 v0 = sA[2*p][r], v1 = sA[2*p+1][r];
        sA[2*p  ][r] = make_float2(v0.x*s.x - v0.y*s.y, v0.x*s.y + v0.y*s.x);
        sA[2*p+1][r] = make_float2(v1.x*s.z - v1.y*s.w, v1.x*s.w + v1.y*s.z);
    }
    fft528<1>(sA[ty], tw, tx);
    const float inv = 1.f / NP;
    for (int e = tid; e < NP*2; e += 256) {
        int r = e >> 1, p = e & 1;
        float2 v0 = sA[2*p][r], v1 = sA[2*p+1][r];
        out4[(r*NPH + c0)/2 + p] = make_float4(v0.x*inv, v0.y*inv, v1.x*inv, v1.y*inv);
    }
}

// P5: two Hermitian half-rows -> packed IFFT, crop, write both output rows.
__global__ void __launch_bounds__(256, 8) k_p5(float* outp) {
    __shared__ float2 tw[TWSZ];
    __shared__ float2 sA[LPB][LSTR];
    int tx = threadIdx.x, ty = threadIdx.y;
    int tid = ty*64 + tx;
    for (int i = tid; i < TWSZ; i += 256) tw[i] = g_tw[i];
    int line = blockIdx.x*LPB + ty;
    int img = line / 256, q = line % 256;
    int o1 = 2*q, o2 = 2*q + 1;
    int r1 = o1 + 8, r2 = o2 + 8;
    const float2* i1 = g_bufB + (size_t)img*NP*NPH + (size_t)r1*NPH;
    const float2* i2 = g_bufB + (size_t)img*NP*NPH + (size_t)r2*NPH;
    for (int m = tx; m < 265; m += 64) {
        float2 B1 = i1[m], B2 = i2[m];
        sA[ty][m] = make_float2(B1.x - B2.y, B1.y + B2.x);
        if (m >= 1 && m <= 263)
            sA[ty][NP - m] = make_float2(B1.x + B2.y, B2.x - B1.y);
    }
    fft528<1>(sA[ty], tw, tx);
    const float inv = 1.f / NP;
    float* d1 = outp + ((size_t)img*512 + o1)*512;
    float* d2 = outp + ((size_t)img*512 + o2)*512;
    for (int j = 8 + tx; j < 520; j += 64) {
        float2 z = sA[ty][j];
        d1[j - 8] = z.x * inv;
        d2[j - 8] = z.y * inv;
    }
}

// ---------------- launch ------------------------------------------------------
extern "C" void kernel_launch(void* const* d_in, const int* in_sizes, int n_in,
                              void* d_out, int out_size) {
    const float* image  = (const float*)d_in[0];
    const float* blurK  = (const float*)d_in[1];
    // d_in[2] = stdn (unused by the reference forward pass)
    const float* wcw    = (const float*)d_in[3];
    const float* wscale = (const float*)d_in[4];
    const float* alpha  = (const float*)d_in[5];
    const float* wts    = (const float*)d_in[6];
    float* outp = (float*)d_out;

    k_band<<<dim3(17, 2, NIMG), 64>>>(image, blurK);
    k_prep<<<1, NP>>>(wcw, wscale, alpha, wts, blurK);
    k_spec<<<dim3(33, NB), NPH>>>(blurK);

    dim3 blk(64, LPB);
    k_p1e<<<(NIMG*264)/LPB, blk>>>(image);
    k_colpass<<<dim3(67, NIMG), blk>>>();
    k_p5<<<(NIMG*256)/LPB, blk>>>(outp);
}

// round 16
// speedup vs baseline: 1.1663x; 1.1432x over previous
#include <cuda_runtime.h>
#include <math.h>

#define NP   528
#define NPH  272        // padded half-width (cols 0..264 valid)
#define NIMG 24
#define NB   8
#define LPB  4
#define LSTR 528        // shared line stride (float2 units)
#define TWSZ 496        // FFT core never indexes tw above 480

// ---------------- scratch (static device globals; no runtime allocation) ----
__device__ float2 g_tw[NP];                          // e^{-2*pi*i*n/528}
__device__ float2 g_bufA[(size_t)NIMG*NP*NPH];       // ping  [img][row][col<265]
__device__ float2 g_bufB[(size_t)NIMG*NP*NPH];       // pong; front also reused as
                                                     // float band-blur [img][528][528]
__device__ float2 g_M[(size_t)NB*NP*NPH];            // collapsed wiener multiplier
__device__ float  g_wn[24*25];                       // normalized wiener filters
__device__ float  g_A[81];                           // filter autocorrelation 9x9
__device__ float  g_r0[NB*17];                       // psf row-proj autocorr
__device__ float  g_r1[NB*17];                       // psf col-proj autocorr
__device__ float  g_ad[4];                           // exp(alpha_d)
__device__ float  g_wt[4];                           // weights_d

// ---------------- helpers ----------------------------------------------------
__device__ __forceinline__ int sympad(int p) {
    return p < 8 ? 7 - p : (p < 520 ? p - 8 : 1031 - p);
}
__device__ __forceinline__ int m528(int x) {
    x %= NP; return x < 0 ? x + NP : x;
}
// unnormalized beta (caller multiplies by 1/r[0]); 0 exactly for 17<=i<=510
__device__ __forceinline__ float betaraw(int i, const float* r) {
    if (i < 17)  return r[i];
    if (i == 527) return r[0];
    if (i > 510) return r[527 - i];
    return 0.f;
}

// all table constants stored in e^{-i*theta} convention (cos, -sin); cmul<DIR>
// conjugates for the inverse transform.
template<int DIR>
__device__ __forceinline__ float2 cmul(float2 a, float2 w) {
    float wi = (DIR < 0) ? w.y : -w.y;
    return make_float2(a.x*w.x - a.y*wi, a.x*wi + a.y*w.x);
}
__device__ __forceinline__ float2 cadd(float2 a, float2 b){ return make_float2(a.x+b.x, a.y+b.y); }
__device__ __forceinline__ float2 csub(float2 a, float2 b){ return make_float2(a.x-b.x, a.y-b.y); }

// radix-4 in place: X_k = sum_n x_n W4^{nk}, W4 = e^{DIR*2*pi*i/4}
template<int DIR>
__device__ __forceinline__ void radix4(float2& a, float2& b, float2& c, float2& d) {
    float2 t0 = cadd(a,c), t1 = csub(a,c), t2 = cadd(b,d), t3 = csub(b,d);
    float2 mi = (DIR < 0) ? make_float2(t3.y, -t3.x) : make_float2(-t3.y, t3.x); // ∓ i*t3
    a = cadd(t0, t2);
    c = csub(t0, t2);
    b = cadd(t1, mi);
    d = csub(t1, mi);
}

#define W16_1 make_float2( 0.923879532511286756f, -0.382683432365089772f)
#define W16_2 make_float2( 0.707106781186547524f, -0.707106781186547524f)
#define W16_3 make_float2( 0.382683432365089772f, -0.923879532511286756f)
#define W16_4 make_float2( 0.f, -1.f)
#define W16_6 make_float2(-0.707106781186547524f, -0.707106781186547524f)
#define W16_9 make_float2(-0.923879532511286756f,  0.382683432365089772f)
#define W3_1  make_float2(-0.5f, -0.866025403784438647f)
#define W3_2  make_float2(-0.5f,  0.866025403784438647f)

// cos/sin(2*pi*m/11), m=1..5 (positive values; signs in the per-k rows)
#define C11_1 ( 0.841253532831181168f)
#define C11_2 ( 0.415415013001886426f)
#define C11_3 (-0.142314838273285140f)
#define C11_4 (-0.654860733945285064f)
#define C11_5 (-0.959492973614497389f)
#define S11_1 ( 0.540640817455597582f)
#define S11_2 ( 0.909631995354518371f)
#define S11_3 ( 0.989821441880932732f)
#define S11_4 ( 0.755749574354258283f)
#define S11_5 ( 0.281732556841429913f)

// ---------------- length-528 DFT, stages 16 (=4x4 register FFT) x 33 (=3x11) --
// 64 threads/line (warp-aligned teams), LPB lines per 256-thread block,
// block-wide __syncthreads (single HW barrier id). Fully IN-PLACE in sA:
// stage 1 owns its column; stage 2 folds its 33 row inputs into registers,
// then a barrier separates reads from scatter writes. DIR=-1 fwd, +1 inv.
// ALL 256 threads of the block must call in lockstep.
template<int DIR>
__device__ void fft528(float2* sA, const float2* tw, int t) {
    __syncthreads();
    // ---- stage 1 (in place): one unit per n2 (t<33): 16-point register FFT
    //      over n1, inter-stage twiddle W528^{k1*n2}; write back to own column.
    if (t < 33) {
        int n2 = t;
        float2 q0[4], q1[4], q2[4], q3[4];
        #pragma unroll
        for (int n2p = 0; n2p < 4; n2p++) {
            float2 a = sA[ n2p     *33 + n2];
            float2 b = sA[(4+n2p)  *33 + n2];
            float2 c = sA[(8+n2p)  *33 + n2];
            float2 d = sA[(12+n2p) *33 + n2];
            radix4<DIR>(a, b, c, d);
            q0[n2p]=a; q1[n2p]=b; q2[n2p]=c; q3[n2p]=d;
        }
        float2 U[16];
        { float2 a=q0[0], b=q0[1], c=q0[2], d=q0[3];
          radix4<DIR>(a,b,c,d); U[0]=a; U[4]=b; U[8]=c; U[12]=d; }
        { float2 a=q1[0];
          float2 b=cmul<DIR>(q1[1], W16_1);
          float2 c=cmul<DIR>(q1[2], W16_2);
          float2 d=cmul<DIR>(q1[3], W16_3);
          radix4<DIR>(a,b,c,d); U[1]=a; U[5]=b; U[9]=c; U[13]=d; }
        { float2 a=q2[0];
          float2 b=cmul<DIR>(q2[1], W16_2);
          float2 c=cmul<DIR>(q2[2], W16_4);
          float2 d=cmul<DIR>(q2[3], W16_6);
          radix4<DIR>(a,b,c,d); U[2]=a; U[6]=b; U[10]=c; U[14]=d; }
        { float2 a=q3[0];
          float2 b=cmul<DIR>(q3[1], W16_3);
          float2 c=cmul<DIR>(q3[2], W16_6);
          float2 d=cmul<DIR>(q3[3], W16_9);
          radix4<DIR>(a,b,c,d); U[3]=a; U[7]=b; U[11]=c; U[15]=d; }
        #pragma unroll
        for (int m = 0; m < 16; m++)
            sA[m*33 + n2] = cmul<DIR>(U[m], tw[m*n2]);   // m*n2 <= 480
    }
    __syncthreads();
    // ---- stage 2: per k1 a 33-point DFT over n2, split 33 = 3 x 11.
    //      Phase A: load row k1 + radix-3 fold + twiddle into v[11] (regs).
    //      Barrier. Phase B: 11-pt conj-pair DFT, scatter-write into sA.
    {
        int k1 = t & 15, k1p = t >> 4;
        bool act = (k1p < 3);
        float2 v[11];
        if (act) {
            float2 w3a, w3b;
            if (k1p == 1)      { w3a = W3_1; w3b = W3_2; }
            else if (k1p == 2) { w3a = W3_2; w3b = W3_1; }
            else               { w3a = make_float2(1.f,0.f); w3b = w3a; }
            const float2* y = sA + k1*33;
            int tstep = 16 * k1p;
            #pragma unroll
            for (int q = 0; q < 11; q++) {
                float2 a = y[q], b = y[11+q], c = y[22+q];
                float2 uu = cadd(a, cadd(cmul<DIR>(b, w3a), cmul<DIR>(c, w3b)));
                v[q] = cmul<DIR>(uu, tw[tstep*q]);       // <= 320
            }
        }
        __syncthreads();
        if (act) {
            float2 v0  = v[0];
            float2 ss1 = cadd(v[1], v[10]), dd1 = csub(v[1], v[10]);
            float2 ss2 = cadd(v[2], v[9]),  dd2 = csub(v[2], v[9]);
            float2 ss3 = cadd(v[3], v[8]),  dd3 = csub(v[3], v[8]);
            float2 ss4 = cadd(v[4], v[7]),  dd4 = csub(v[4], v[7]);
            float2 ss5 = cadd(v[5], v[6]),  dd5 = csub(v[5], v[6]);
            sA[k1 + 16*k1p] = make_float2(
                v0.x + ss1.x + ss2.x + ss3.x + ss4.x + ss5.x,
                v0.y + ss1.y + ss2.y + ss3.y + ss4.y + ss5.y);
            #define OUTIDX(kk) (k1 + 16*(k1p + 3*(kk)))
            #define DFT11P(kk, cA,cB,cC,cD,cE, sP,sQ,sR,sS,sT) { \
                float Ax = fmaf(cA,ss1.x, fmaf(cB,ss2.x, fmaf(cC,ss3.x, fmaf(cD,ss4.x, fmaf(cE,ss5.x, v0.x))))); \
                float Ay = fmaf(cA,ss1.y, fmaf(cB,ss2.y, fmaf(cC,ss3.y, fmaf(cD,ss4.y, fmaf(cE,ss5.y, v0.y))))); \
                float Sx = fmaf(sP,dd1.x, fmaf(sQ,dd2.x, fmaf(sR,dd3.x, fmaf(sS,dd4.x, sT*dd5.x)))); \
                float Sy = fmaf(sP,dd1.y, fmaf(sQ,dd2.y, fmaf(sR,dd3.y, fmaf(sS,dd4.y, sT*dd5.y)))); \
                if (DIR < 0) { \
                    sA[OUTIDX(kk)]      = make_float2(Ax + Sy, Ay - Sx); \
                    sA[OUTIDX(11-(kk))] = make_float2(Ax - Sy, Ay + Sx); \
                } else { \
                    sA[OUTIDX(kk)]      = make_float2(Ax - Sy, Ay + Sx); \
                    sA[OUTIDX(11-(kk))] = make_float2(Ax + Sy, Ay - Sx); \
                } }
            DFT11P(1, C11_1,C11_2,C11_3,C11_4,C11_5,  S11_1, S11_2, S11_3, S11_4, S11_5)
            DFT11P(2, C11_2,C11_4,C11_5,C11_3,C11_1,  S11_2, S11_4,-S11_5,-S11_3,-S11_1)
            DFT11P(3, C11_3,C11_5,C11_2,C11_1,C11_4,  S11_3,-S11_5,-S11_2, S11_1, S11_4)
            DFT11P(4, C11_4,C11_3,C11_1,C11_5,C11_2,  S11_4,-S11_3, S11_1, S11_5,-S11_2)
            DFT11P(5, C11_5,C11_1,C11_4,C11_2,C11_3,  S11_5,-S11_1, S11_4,-S11_2, S11_3)
            #undef DFT11P
            #undef OUTIDX
        }
    }
    __syncthreads();
}

// ---------------- prep kernel --------------------------------------------------
__global__ void k_prep(const float* wcw, const float* wscale, const float* alpha,
                       const float* wts, const float* blurK) {
    int t = threadIdx.x;
    if (t < NP) {
        double a = -6.28318530717958647692528676655900577 * (double)t / (double)NP;
        g_tw[t] = make_float2((float)cos(a), (float)sin(a));
    }
    if (t < 24) {
        float m = 0.f;
        for (int i = 0; i < 25; i++) m += wcw[t*25 + i];
        m *= (1.f/25.f);
        float ss = 0.f;
        for (int i = 0; i < 25; i++) { float d = wcw[t*25+i] - m; ss += d*d; }
        float s = wscale[t] / sqrtf(ss);
        for (int i = 0; i < 25; i++) g_wn[t*25 + i] = (wcw[t*25+i] - m) * s;
    }
    if (t >= 96 && t < 104) {
        int b = t - 96;
        float p0[17], p1[17];
        for (int u = 0; u < 17; u++) { p0[u] = 0.f; p1[u] = 0.f; }
        for (int u = 0; u < 17; u++)
            for (int v = 0; v < 17; v++) {
                float pv = blurK[b*289 + u*17 + v];
                p0[u] += pv; p1[v] += pv;
            }
        for (int n = 0; n < 17; n++) {
            float a0 = 0.f, a1 = 0.f;
            for (int m2 = 0; m2 + n < 17; m2++) {
                a0 += p0[m2] * p0[m2+n];
                a1 += p1[m2] * p1[m2+n];
            }
            g_r0[b*17 + n] = a0;
            g_r1[b*17 + n] = a1;
        }
    }
    if (t == 511) {
        for (int d = 0; d < 4; d++) { g_ad[d] = expf(alpha[d]); g_wt[d] = wts[d]; }
    }
    __syncthreads();
    if (t < 81) {
        int du = t/9 - 4, dv = t%9 - 4;
        float acc = 0.f;
        for (int f = 0; f < 24; f++)
            for (int u = 0; u < 5; u++)
                for (int v = 0; v < 5; v++) {
                    int uu = u + du, vv = v + dv;
                    if (uu >= 0 && uu < 5 && vv >= 0 && vv < 5)
                        acc += g_wn[f*25 + uu*5 + vv] * g_wn[f*25 + u*5 + v];
                }
        g_A[t] = acc;
    }
}

// ---------------- fused spectrum kernel: rv + Greg + M  ----------------------
// grid (33, NB), 272 threads; 16 w1 rows per block.
__global__ void k_spec(const float* blurK) {
    __shared__ float psf[289];
    __shared__ float A[81];
    __shared__ float twc[NP];
    int bx = blockIdx.x;     // 0..32 (w1 chunk)
    int b  = blockIdx.y;
    int w2 = threadIdx.x;    // 272 threads
    for (int i = w2; i < 289; i += 272) psf[i] = blurK[b*289 + i];
    if (w2 < 81) A[w2] = g_A[w2];
    for (int i = w2; i < NP; i += 272) twc[i] = g_tw[i].x;
    __syncthreads();
    if (w2 >= 265) return;
    float2 rv[17];
    {
        float2 wv[17];
        int ix = m528(-8 * w2);
        #pragma unroll
        for (int v = 0; v < 17; v++) {
            wv[v] = g_tw[ix];
            ix += w2; if (ix >= NP) ix -= NP;
        }
        #pragma unroll
        for (int u = 0; u < 17; u++) {
            float re = 0.f, im = 0.f;
            #pragma unroll
            for (int v = 0; v < 17; v++) {
                float p = psf[u*17 + v];
                re += p * wv[v].x; im += p * wv[v].y;
            }
            rv[u] = make_float2(re, im);
        }
    }
    for (int w1c = 0; w1c < 16; w1c++) {
        int w1 = bx*16 + w1c;
        float gacc = 0.f;
        {
            int ib = m528(-4 * (w1 + w2));
            #pragma unroll
            for (int du = 0; du < 4; du++) {
                int ix = ib;
                #pragma unroll
                for (int dv = 0; dv < 9; dv++) {
                    gacc += A[du*9 + dv] * twc[ix];
                    ix += w2; if (ix >= NP) ix -= NP;
                }
                ib += w1; if (ib >= NP) ib -= NP;
            }
            int ix = ib;
            #pragma unroll
            for (int dv = 0; dv < 4; dv++) {
                gacc += A[36 + dv] * twc[ix];
                ix += w2; if (ix >= NP) ix -= NP;
            }
        }
        float gg = fmaf(2.f, gacc, A[40]);
        float kr = 0.f, ki = 0.f;
        int ix = m528(-8 * w1);
        #pragma unroll
        for (int u = 0; u < 17; u++) {
            float2 w = g_tw[ix];
            ix += w1; if (ix >= NP) ix -= NP;
            kr += w.x*rv[u].x - w.y*rv[u].y;
            ki += w.x*rv[u].y + w.y*rv[u].x;
        }
        float s2 = kr*kr + ki*ki;
        float acc = 0.f;
        #pragma unroll
        for (int d = 0; d < 4; d++) acc += __fdividef(g_wt[d], fmaf(g_ad[d], gg, s2));
        g_M[(size_t)b*NP*NPH + (size_t)w1*NPH + w2] = make_float2(kr*acc, -ki*acc);
    }
}

// ---------------- band blur (spatial 17x17 circular conv, band only) ---------
__global__ void __launch_bounds__(64) k_band(const float* image, const float* blurK) {
    __shared__ float psf_s[289];
    __shared__ float tile[2640];
    int t = threadIdx.x;
    int side = blockIdx.y;       // 0,1
    int img = blockIdx.z;        // 0..23
    int b = img / 3;
    for (int i = t; i < 289; i += 64) psf_s[i] = blurK[b*289 + i];
    const float* im = image + (size_t)img*512*512;
    float* bb = (float*)g_bufB + (size_t)img*528*528;
    if (blockIdx.x < 9) {
        int c0 = blockIdx.x * 64;
        int base = side ? 511 : 0;
        for (int e = t; e < 33*80; e += 64) {
            int i = e / 80, j = e % 80;
            int rr = (base - 8 + i + 528) % 528;
            int cc = (c0 - 8 + j + 528) % 528;
            tile[i*80 + j] = im[sympad(rr)*512 + sympad(cc)];
        }
        __syncthreads();
        int c = c0 + t;
        if (c >= 528) return;
        float col[33];
        float acc[17];
        #pragma unroll
        for (int r = 0; r < 17; r++) acc[r] = 0.f;
        for (int v = 0; v < 17; v++) {
            #pragma unroll
            for (int i = 0; i < 33; i++) col[i] = tile[i*80 + t + 16 - v];
            #pragma unroll
            for (int u = 0; u < 17; u++) {
                float s = psf_s[u*17 + v];
                #pragma unroll
                for (int r = 0; r < 17; r++)
                    acc[r] = fmaf(s, col[r - u + 16], acc[r]);
            }
        }
        #pragma unroll
        for (int r = 0; r < 17; r++) bb[(size_t)(base + r)*528 + c] = acc[r];
    } else {
        int rg = blockIdx.x - 9;     // 0..7
        int r0 = 17 + rg*64;
        int basec = side ? 511 : 0;
        for (int e = t; e < 80*33; e += 64) {
            int i = e / 33, j = e % 33;
            int rr = (r0 - 8 + i) % 528;
            int cc = (basec - 8 + j + 528) % 528;
            tile[i*33 + j] = im[sympad(rr)*512 + sympad(cc)];
        }
        __syncthreads();
        int r = r0 + t;
        if (r > 510) return;
        float rowv[33];
        float acc[17];
        #pragma unroll
        for (int c = 0; c < 17; c++) acc[c] = 0.f;
        for (int u = 0; u < 17; u++) {
            #pragma unroll
            for (int j = 0; j < 33; j++) rowv[j] = tile[(t + 16 - u)*33 + j];
            #pragma unroll
            for (int v = 0; v < 17; v++) {
                float s = psf_s[u*17 + v];
                #pragma unroll
                for (int c = 0; c < 17; c++)
                    acc[c] = fmaf(s, rowv[c - v + 16], acc[c]);
            }
        }
        #pragma unroll
        for (int c = 0; c < 17; c++) bb[(size_t)r*528 + basec + c] = acc[c];
    }
}

// ---------------- big passes --------------------------------------------------
// P1E: symmetric-pad + inline edgetaper mix (blur from band buffer), pack two
// real rows, one forward FFT, Hermitian unpack -> bufA.
__global__ void __launch_bounds__(256, 6) k_p1e(const float* image) {
    __shared__ float2 tw[TWSZ];
    __shared__ float2 sA[LPB][LSTR];
    int tx = threadIdx.x, ty = threadIdx.y;
    int tid = ty*64 + tx;
    for (int i = tid; i < TWSZ; i += 256) tw[i] = g_tw[i];
    int line = blockIdx.x*LPB + ty;           // pair index
    int img = line / 264, q = line % 264;
    int r1 = 2*q, r2 = 2*q + 1;
    int b = img / 3;
    const float* ar0 = g_r0 + b*17;
    const float* ar1 = g_r1 + b*17;
    float inv0 = 1.f / ar0[0];
    float inv1 = 1.f / ar1[0];
    float b01 = betaraw(r1, ar0) * inv0;
    float b02 = betaraw(r2, ar0) * inv0;
    const float* src1 = image + ((size_t)img*512 + sympad(r1))*512;
    const float* src2 = image + ((size_t)img*512 + sympad(r2))*512;
    const float* bb1 = (const float*)g_bufB + ((size_t)img*528 + r1)*528;
    const float* bb2 = (const float*)g_bufB + ((size_t)img*528 + r2)*528;
    for (int j = tx; j < NP; j += 64) {
        float b1j = betaraw(j, ar1) * inv1;
        float a1 = (1.f - b01) * (1.f - b1j);
        float a2 = (1.f - b02) * (1.f - b1j);
        int sj = sympad(j);
        float x1 = src1[sj], x2 = src2[sj];
        if (a1 != 1.f) x1 = a1 * x1 + (1.f - a1) * bb1[j];
        if (a2 != 1.f) x2 = a2 * x2 + (1.f - a2) * bb2[j];
        sA[ty][j] = make_float2(x1, x2);
    }
    fft528<-1>(sA[ty], tw, tx);
    float2* d1 = g_bufA + (size_t)img*NP*NPH + (size_t)r1*NPH;
    float2* d2 = g_bufA + (size_t)img*NP*NPH + (size_t)r2*NPH;
    for (int k = tx; k < 265; k += 64) {
        float2 Zk = sA[ty][k];
        float2 Zm = sA[ty][(NP - k) % NP];
        d1[k] = make_float2(0.5f*(Zk.x + Zm.x), 0.5f*(Zk.y - Zm.y));
        d2[k] = make_float2(0.5f*(Zk.y + Zm.y), 0.5f*(Zm.x - Zk.x));
    }
}

// Column pass over half-width columns: col FFT, multiply spectrum M,
// col IFFT (x 1/528). bufA -> bufB. float4 global I/O.
__global__ void __launch_bounds__(256, 6) k_colpass() {
    __shared__ float2 tw[TWSZ];
    __shared__ float2 sA[LPB][LSTR];
    int tx = threadIdx.x, ty = threadIdx.y;
    int tid = ty*64 + tx;
    for (int i = tid; i < TWSZ; i += 256) tw[i] = g_tw[i];
    int img = blockIdx.y;
    int c0  = blockIdx.x * LPB;
    int b   = img / 3;
    const float4* in4  = (const float4*)(g_bufA + (size_t)img * NP * NPH);
    float4*       out4 = (float4*)(g_bufB + (size_t)img * NP * NPH);
    const float4* spec4 = (const float4*)(g_M + (size_t)b * NP * NPH);
    for (int e = tid; e < NP*2; e += 256) {
        int r = e >> 1, p = e & 1;
        float4 v = in4[(r*NPH + c0)/2 + p];
        sA[2*p  ][r] = make_float2(v.x, v.y);
        sA[2*p+1][r] = make_float2(v.z, v.w);
    }
    fft528<-1>(sA[ty], tw, tx);
    for (int e = tid; e < NP*2; e += 256) {
        int r = e >> 1, p = e & 1;
        float4 s = spec4[(r*NPH + c0)/2 + p];
        float2 v0 = sA[2*p][r], v1 = sA[2*p+1][r];
        sA[2*p  ][r] = make_float2(v0.x*s.x - v0.y*s.y, v0.x*s.y + v0.y*s.x);
        sA[2*p+1][r] = make_float2(v1.x*s.z - v1.y*s.w, v1.x*s.w + v1.y*s.z);
    }
    fft528<1>(sA[ty], tw, tx);
    const float inv = 1.f / NP;
    for (int e = tid; e < NP*2; e += 256) {
        int r = e >> 1, p = e & 1;
        float2 v0 = sA[2*p][r], v1 = sA[2*p+1][r];
        out4[(r*NPH + c0)/2 + p] = make_float4(v0.x*inv, v0.y*inv, v1.x*inv, v1.y*inv);
    }
}

// P5: two Hermitian half-rows -> packed IFFT, crop, write both output rows.
__global__ void __launch_bounds__(256, 6) k_p5(float* outp) {
    __shared__ float2 tw[TWSZ];
    __shared__ float2 sA[LPB][LSTR];
    int tx = threadIdx.x, ty = threadIdx.y;
    int tid = ty*64 + tx;
    for (int i = tid; i < TWSZ; i += 256) tw[i] = g_tw[i];
    int line = blockIdx.x*LPB + ty;
    int img = line / 256, q = line % 256;
    int o1 = 2*q, o2 = 2*q + 1;
    int r1 = o1 + 8, r2 = o2 + 8;
    const float2* i1 = g_bufB + (size_t)img*NP*NPH + (size_t)r1*NPH;
    const float2* i2 = g_bufB + (size_t)img*NP*NPH + (size_t)r2*NPH;
    for (int m = tx; m < 265; m += 64) {
        float2 B1 = i1[m], B2 = i2[m];
        sA[ty][m] = make_float2(B1.x - B2.y, B1.y + B2.x);
        if (m >= 1 && m <= 263)
            sA[ty][NP - m] = make_float2(B1.x + B2.y, B2.x - B1.y);
    }
    fft528<1>(sA[ty], tw, tx);
    const float inv = 1.f / NP;
    float* d1 = outp + ((size_t)img*512 + o1)*512;
    float* d2 = outp + ((size_t)img*512 + o2)*512;
    for (int j = 8 + tx; j < 520; j += 64) {
        float2 z = sA[ty][j];
        d1[j - 8] = z.x * inv;
        d2[j - 8] = z.y * inv;
    }
}

// ---------------- launch ------------------------------------------------------
extern "C" void kernel_launch(void* const* d_in, const int* in_sizes, int n_in,
                              void* d_out, int out_size) {
    const float* image  = (const float*)d_in[0];
    const float* blurK  = (const float*)d_in[1];
    // d_in[2] = stdn (unused by the reference forward pass)
    const float* wcw    = (const float*)d_in[3];
    const float* wscale = (const float*)d_in[4];
    const float* alpha  = (const float*)d_in[5];
    const float* wts    = (const float*)d_in[6];
    float* outp = (float*)d_out;

    k_band<<<dim3(17, 2, NIMG), 64>>>(image, blurK);
    k_prep<<<1, NP>>>(wcw, wscale, alpha, wts, blurK);
    k_spec<<<dim3(33, NB), NPH>>>(blurK);

    dim3 blk(64, LPB);
    k_p1e<<<(NIMG*264)/LPB, blk>>>(image);
    k_colpass<<<dim3(67, NIMG), blk>>>();
    k_p5<<<(NIMG*256)/LPB, blk>>>(outp);
}

// round 17
// speedup vs baseline: 1.1858x; 1.0167x over previous
#include <cuda_runtime.h>
#include <math.h>

#define NP   528
#define NPH  272        // padded half-width (cols 0..264 valid)
#define NIMG 24
#define NB   8
#define LPB  4
#define LSTR 528        // shared line stride (float2 units)
#define TWSZ 496        // FFT core never indexes tw above 495

// ---------------- scratch (static device globals; no runtime allocation) ----
__device__ float2 g_tw[NP];                          // e^{-2*pi*i*n/528}
__device__ float2 g_bufA[(size_t)NIMG*NP*NPH];       // ping  [img][row][col<265]
__device__ float2 g_bufB[(size_t)NIMG*NP*NPH];       // pong; front also reused as
                                                     // float band-blur [img][528][528]
__device__ float2 g_M[(size_t)NB*NP*NPH];            // collapsed wiener multiplier
__device__ float  g_wn[24*25];                       // normalized wiener filters
__device__ float  g_A[81];                           // filter autocorrelation 9x9
__device__ float  g_r0[NB*17];                       // psf row-proj autocorr
__device__ float  g_r1[NB*17];                       // psf col-proj autocorr
__device__ float  g_ad[4];                           // exp(alpha_d)
__device__ float  g_wt[4];                           // weights_d

// ---------------- helpers ----------------------------------------------------
__device__ __forceinline__ int sympad(int p) {
    return p < 8 ? 7 - p : (p < 520 ? p - 8 : 1031 - p);
}
__device__ __forceinline__ int m528(int x) {
    x %= NP; return x < 0 ? x + NP : x;
}
// unnormalized beta (caller multiplies by 1/r[0]); 0 exactly for 17<=i<=510
__device__ __forceinline__ float betaraw(int i, const float* r) {
    if (i < 17)  return r[i];
    if (i == 527) return r[0];
    if (i > 510) return r[527 - i];
    return 0.f;
}

// all table constants stored in e^{-i*theta} convention (cos, -sin); cmul<DIR>
// conjugates for the inverse transform.
template<int DIR>
__device__ __forceinline__ float2 cmul(float2 a, float2 w) {
    float wi = (DIR < 0) ? w.y : -w.y;
    return make_float2(a.x*w.x - a.y*wi, a.x*wi + a.y*w.x);
}
__device__ __forceinline__ float2 cadd(float2 a, float2 b){ return make_float2(a.x+b.x, a.y+b.y); }
__device__ __forceinline__ float2 csub(float2 a, float2 b){ return make_float2(a.x-b.x, a.y-b.y); }

// radix-4 in place: X_k = sum_n x_n W4^{nk}, W4 = e^{DIR*2*pi*i/4}
template<int DIR>
__device__ __forceinline__ void radix4(float2& a, float2& b, float2& c, float2& d) {
    float2 t0 = cadd(a,c), t1 = csub(a,c), t2 = cadd(b,d), t3 = csub(b,d);
    float2 mi = (DIR < 0) ? make_float2(t3.y, -t3.x) : make_float2(-t3.y, t3.x); // ∓ i*t3
    a = cadd(t0, t2);
    c = csub(t0, t2);
    b = cadd(t1, mi);
    d = csub(t1, mi);
}

#define W16_1 make_float2( 0.923879532511286756f, -0.382683432365089772f)
#define W16_2 make_float2( 0.707106781186547524f, -0.707106781186547524f)
#define W16_3 make_float2( 0.382683432365089772f, -0.923879532511286756f)
#define W16_4 make_float2( 0.f, -1.f)
#define W16_6 make_float2(-0.707106781186547524f, -0.707106781186547524f)
#define W16_9 make_float2(-0.923879532511286756f,  0.382683432365089772f)
#define W3_1  make_float2(-0.5f, -0.866025403784438647f)
#define W3_2  make_float2(-0.5f,  0.866025403784438647f)

// cos/sin(2*pi*m/11), m=1..5 (positive values; signs in the per-k rows)
#define C11_1 ( 0.841253532831181168f)
#define C11_2 ( 0.415415013001886426f)
#define C11_3 (-0.142314838273285140f)
#define C11_4 (-0.654860733945285064f)
#define C11_5 (-0.959492973614497389f)
#define S11_1 ( 0.540640817455597582f)
#define S11_2 ( 0.909631995354518371f)
#define S11_3 ( 0.989821441880932732f)
#define S11_4 ( 0.755749574354258283f)
#define S11_5 ( 0.281732556841429913f)

// ---------------- length-528 DFT, stages 16 (=4x4 register FFT) x 33 (=3x11) --
// 64 threads/line (warp-aligned teams), LPB lines per 256-thread block,
// block-wide __syncthreads (single HW barrier id). Fully IN-PLACE in sA.
// Stage 1: warp 0 (t<32, uniform branch) runs the 16-pt register FFT for
// column n2=t; warp 1 lanes 0..15 (32<=t<48) handle column 32 via a direct
// 16-term DFT, one output per lane (loads broadcast, stores conflict-free).
// Stage 2 folds its 33 row inputs into registers, then a barrier separates
// reads from scatter writes. DIR=-1 fwd, +1 inv (unscaled).
// ALL 256 threads of the block must call in lockstep.
template<int DIR>
__device__ void fft528(float2* sA, const float2* tw, int t) {
    __syncthreads();
    if (t < 32) {
        int n2 = t;
        float2 q0[4], q1[4], q2[4], q3[4];
        #pragma unroll
        for (int n2p = 0; n2p < 4; n2p++) {
            float2 a = sA[ n2p     *33 + n2];
            float2 b = sA[(4+n2p)  *33 + n2];
            float2 c = sA[(8+n2p)  *33 + n2];
            float2 d = sA[(12+n2p) *33 + n2];
            radix4<DIR>(a, b, c, d);
            q0[n2p]=a; q1[n2p]=b; q2[n2p]=c; q3[n2p]=d;
        }
        float2 U[16];
        { float2 a=q0[0], b=q0[1], c=q0[2], d=q0[3];
          radix4<DIR>(a,b,c,d); U[0]=a; U[4]=b; U[8]=c; U[12]=d; }
        { float2 a=q1[0];
          float2 b=cmul<DIR>(q1[1], W16_1);
          float2 c=cmul<DIR>(q1[2], W16_2);
          float2 d=cmul<DIR>(q1[3], W16_3);
          radix4<DIR>(a,b,c,d); U[1]=a; U[5]=b; U[9]=c; U[13]=d; }
        { float2 a=q2[0];
          float2 b=cmul<DIR>(q2[1], W16_2);
          float2 c=cmul<DIR>(q2[2], W16_4);
          float2 d=cmul<DIR>(q2[3], W16_6);
          radix4<DIR>(a,b,c,d); U[2]=a; U[6]=b; U[10]=c; U[14]=d; }
        { float2 a=q3[0];
          float2 b=cmul<DIR>(q3[1], W16_3);
          float2 c=cmul<DIR>(q3[2], W16_6);
          float2 d=cmul<DIR>(q3[3], W16_9);
          radix4<DIR>(a,b,c,d); U[3]=a; U[7]=b; U[11]=c; U[15]=d; }
        #pragma unroll
        for (int m = 0; m < 16; m++)
            sA[m*33 + n2] = cmul<DIR>(U[m], tw[m*n2]);   // m*n2 <= 480
    } else if (t < 48) {
        // column n2 = 32: direct 16-pt DFT, one output per lane.
        // W16^j = tw[33*j]; all loads are warp-broadcast of the same address;
        // all lanes load the full column before any lane's store (in-order
        // within the warp), so the in-place update is hazard-free.
        int m = t - 32;
        float2 acc = sA[32];                             // n1 = 0 term
        #pragma unroll
        for (int n1 = 1; n1 < 16; n1++) {
            float2 x = sA[n1*33 + 32];
            int idx = 33 * ((m * n1) & 15);              // <= 495
            acc = cadd(acc, cmul<DIR>(x, tw[idx]));
        }
        sA[m*33 + 32] = cmul<DIR>(acc, tw[m*32]);        // <= 480
    }
    __syncthreads();
    // ---- stage 2: per k1 a 33-point DFT over n2, split 33 = 3 x 11.
    //      Phase A: load row k1 + radix-3 fold + twiddle into v[11] (regs).
    //      Barrier. Phase B: 11-pt conj-pair DFT, scatter-write into sA.
    {
        int k1 = t & 15, k1p = t >> 4;
        bool act = (k1p < 3);
        float2 v[11];
        if (act) {
            float2 w3a, w3b;
            if (k1p == 1)      { w3a = W3_1; w3b = W3_2; }
            else if (k1p == 2) { w3a = W3_2; w3b = W3_1; }
            else               { w3a = make_float2(1.f,0.f); w3b = w3a; }
            const float2* y = sA + k1*33;
            int tstep = 16 * k1p;
            #pragma unroll
            for (int q = 0; q < 11; q++) {
                float2 a = y[q], b = y[11+q], c = y[22+q];
                float2 uu = cadd(a, cadd(cmul<DIR>(b, w3a), cmul<DIR>(c, w3b)));
                v[q] = cmul<DIR>(uu, tw[tstep*q]);       // <= 320
            }
        }
        __syncthreads();
        if (act) {
            float2 v0  = v[0];
            float2 ss1 = cadd(v[1], v[10]), dd1 = csub(v[1], v[10]);
            float2 ss2 = cadd(v[2], v[9]),  dd2 = csub(v[2], v[9]);
            float2 ss3 = cadd(v[3], v[8]),  dd3 = csub(v[3], v[8]);
            float2 ss4 = cadd(v[4], v[7]),  dd4 = csub(v[4], v[7]);
            float2 ss5 = cadd(v[5], v[6]),  dd5 = csub(v[5], v[6]);
            sA[k1 + 16*k1p] = make_float2(
                v0.x + ss1.x + ss2.x + ss3.x + ss4.x + ss5.x,
                v0.y + ss1.y + ss2.y + ss3.y + ss4.y + ss5.y);
            #define OUTIDX(kk) (k1 + 16*(k1p + 3*(kk)))
            #define DFT11P(kk, cA,cB,cC,cD,cE, sP,sQ,sR,sS,sT) { \
                float Ax = fmaf(cA,ss1.x, fmaf(cB,ss2.x, fmaf(cC,ss3.x, fmaf(cD,ss4.x, fmaf(cE,ss5.x, v0.x))))); \
                float Ay = fmaf(cA,ss1.y, fmaf(cB,ss2.y, fmaf(cC,ss3.y, fmaf(cD,ss4.y, fmaf(cE,ss5.y, v0.y))))); \
                float Sx = fmaf(sP,dd1.x, fmaf(sQ,dd2.x, fmaf(sR,dd3.x, fmaf(sS,dd4.x, sT*dd5.x)))); \
                float Sy = fmaf(sP,dd1.y, fmaf(sQ,dd2.y, fmaf(sR,dd3.y, fmaf(sS,dd4.y, sT*dd5.y)))); \
                if (DIR < 0) { \
                    sA[OUTIDX(kk)]      = make_float2(Ax + Sy, Ay - Sx); \
                    sA[OUTIDX(11-(kk))] = make_float2(Ax - Sy, Ay + Sx); \
                } else { \
                    sA[OUTIDX(kk)]      = make_float2(Ax - Sy, Ay + Sx); \
                    sA[OUTIDX(11-(kk))] = make_float2(Ax + Sy, Ay - Sx); \
                } }
            DFT11P(1, C11_1,C11_2,C11_3,C11_4,C11_5,  S11_1, S11_2, S11_3, S11_4, S11_5)
            DFT11P(2, C11_2,C11_4,C11_5,C11_3,C11_1,  S11_2, S11_4,-S11_5,-S11_3,-S11_1)
            DFT11P(3, C11_3,C11_5,C11_2,C11_1,C11_4,  S11_3,-S11_5,-S11_2, S11_1, S11_4)
            DFT11P(4, C11_4,C11_3,C11_1,C11_5,C11_2,  S11_4,-S11_3, S11_1, S11_5,-S11_2)
            DFT11P(5, C11_5,C11_1,C11_4,C11_2,C11_3,  S11_5,-S11_1, S11_4,-S11_2, S11_3)
            #undef DFT11P
            #undef OUTIDX
        }
    }
    __syncthreads();
}

// ---------------- prep kernel --------------------------------------------------
__global__ void k_prep(const float* wcw, const float* wscale, const float* alpha,
                       const float* wts, const float* blurK) {
    int t = threadIdx.x;
    if (t < NP) {
        double a = -6.28318530717958647692528676655900577 * (double)t / (double)NP;
        g_tw[t] = make_float2((float)cos(a), (float)sin(a));
    }
    if (t < 24) {
        float m = 0.f;
        for (int i = 0; i < 25; i++) m += wcw[t*25 + i];
        m *= (1.f/25.f);
        float ss = 0.f;
        for (int i = 0; i < 25; i++) { float d = wcw[t*25+i] - m; ss += d*d; }
        float s = wscale[t] / sqrtf(ss);
        for (int i = 0; i < 25; i++) g_wn[t*25 + i] = (wcw[t*25+i] - m) * s;
    }
    if (t >= 96 && t < 104) {
        int b = t - 96;
        float p0[17], p1[17];
        for (int u = 0; u < 17; u++) { p0[u] = 0.f; p1[u] = 0.f; }
        for (int u = 0; u < 17; u++)
            for (int v = 0; v < 17; v++) {
                float pv = blurK[b*289 + u*17 + v];
                p0[u] += pv; p1[v] += pv;
            }
        for (int n = 0; n < 17; n++) {
            float a0 = 0.f, a1 = 0.f;
            for (int m2 = 0; m2 + n < 17; m2++) {
                a0 += p0[m2] * p0[m2+n];
                a1 += p1[m2] * p1[m2+n];
            }
            g_r0[b*17 + n] = a0;
            g_r1[b*17 + n] = a1;
        }
    }
    if (t == 511) {
        for (int d = 0; d < 4; d++) { g_ad[d] = expf(alpha[d]); g_wt[d] = wts[d]; }
    }
    __syncthreads();
    if (t < 81) {
        int du = t/9 - 4, dv = t%9 - 4;
        float acc = 0.f;
        for (int f = 0; f < 24; f++)
            for (int u = 0; u < 5; u++)
                for (int v = 0; v < 5; v++) {
                    int uu = u + du, vv = v + dv;
                    if (uu >= 0 && uu < 5 && vv >= 0 && vv < 5)
                        acc += g_wn[f*25 + uu*5 + vv] * g_wn[f*25 + u*5 + v];
                }
        g_A[t] = acc;
    }
}

// ---------------- fused spectrum kernel: rv + Greg + M  ----------------------
// grid (33, NB), 272 threads; 16 w1 rows per block.
__global__ void k_spec(const float* blurK) {
    __shared__ float psf[289];
    __shared__ float A[81];
    __shared__ float twc[NP];
    int bx = blockIdx.x;     // 0..32 (w1 chunk)
    int b  = blockIdx.y;
    int w2 = threadIdx.x;    // 272 threads
    for (int i = w2; i < 289; i += 272) psf[i] = blurK[b*289 + i];
    if (w2 < 81) A[w2] = g_A[w2];
    for (int i = w2; i < NP; i += 272) twc[i] = g_tw[i].x;
    __syncthreads();
    if (w2 >= 265) return;
    float2 rv[17];
    {
        float2 wv[17];
        int ix = m528(-8 * w2);
        #pragma unroll
        for (int v = 0; v < 17; v++) {
            wv[v] = g_tw[ix];
            ix += w2; if (ix >= NP) ix -= NP;
        }
        #pragma unroll
        for (int u = 0; u < 17; u++) {
            float re = 0.f, im = 0.f;
            #pragma unroll
            for (int v = 0; v < 17; v++) {
                float p = psf[u*17 + v];
                re += p * wv[v].x; im += p * wv[v].y;
            }
            rv[u] = make_float2(re, im);
        }
    }
    for (int w1c = 0; w1c < 16; w1c++) {
        int w1 = bx*16 + w1c;
        float gacc = 0.f;
        {
            int ib = m528(-4 * (w1 + w2));
            #pragma unroll
            for (int du = 0; du < 4; du++) {
                int ix = ib;
                #pragma unroll
                for (int dv = 0; dv < 9; dv++) {
                    gacc += A[du*9 + dv] * twc[ix];
                    ix += w2; if (ix >= NP) ix -= NP;
                }
                ib += w1; if (ib >= NP) ib -= NP;
            }
            int ix = ib;
            #pragma unroll
            for (int dv = 0; dv < 4; dv++) {
                gacc += A[36 + dv] * twc[ix];
                ix += w2; if (ix >= NP) ix -= NP;
            }
        }
        float gg = fmaf(2.f, gacc, A[40]);
        float kr = 0.f, ki = 0.f;
        int ix = m528(-8 * w1);
        #pragma unroll
        for (int u = 0; u < 17; u++) {
            float2 w = g_tw[ix];
            ix += w1; if (ix >= NP) ix -= NP;
            kr += w.x*rv[u].x - w.y*rv[u].y;
            ki += w.x*rv[u].y + w.y*rv[u].x;
        }
        float s2 = kr*kr + ki*ki;
        float acc = 0.f;
        #pragma unroll
        for (int d = 0; d < 4; d++) acc += __fdividef(g_wt[d], fmaf(g_ad[d], gg, s2));
        g_M[(size_t)b*NP*NPH + (size_t)w1*NPH + w2] = make_float2(kr*acc, -ki*acc);
    }
}

// ---------------- band blur (spatial 17x17 circular conv, band only) ---------
__global__ void __launch_bounds__(64) k_band(const float* image, const float* blurK) {
    __shared__ float psf_s[289];
    __shared__ float tile[2640];
    int t = threadIdx.x;
    int side = blockIdx.y;       // 0,1
    int img = blockIdx.z;        // 0..23
    int b = img / 3;
    for (int i = t; i < 289; i += 64) psf_s[i] = blurK[b*289 + i];
    const float* im = image + (size_t)img*512*512;
    float* bb = (float*)g_bufB + (size_t)img*528*528;
    if (blockIdx.x < 9) {
        int c0 = blockIdx.x * 64;
        int base = side ? 511 : 0;
        for (int e = t; e < 33*80; e += 64) {
            int i = e / 80, j = e % 80;
            int rr = (base - 8 + i + 528) % 528;
            int cc = (c0 - 8 + j + 528) % 528;
            tile[i*80 + j] = im[sympad(rr)*512 + sympad(cc)];
        }
        __syncthreads();
        int c = c0 + t;
        if (c >= 528) return;
        float col[33];
        float acc[17];
        #pragma unroll
        for (int r = 0; r < 17; r++) acc[r] = 0.f;
        for (int v = 0; v < 17; v++) {
            #pragma unroll
            for (int i = 0; i < 33; i++) col[i] = tile[i*80 + t + 16 - v];
            #pragma unroll
            for (int u = 0; u < 17; u++) {
                float s = psf_s[u*17 + v];
                #pragma unroll
                for (int r = 0; r < 17; r++)
                    acc[r] = fmaf(s, col[r - u + 16], acc[r]);
            }
        }
        #pragma unroll
        for (int r = 0; r < 17; r++) bb[(size_t)(base + r)*528 + c] = acc[r];
    } else {
        int rg = blockIdx.x - 9;     // 0..7
        int r0 = 17 + rg*64;
        int basec = side ? 511 : 0;
        for (int e = t; e < 80*33; e += 64) {
            int i = e / 33, j = e % 33;
            int rr = (r0 - 8 + i) % 528;
            int cc = (basec - 8 + j + 528) % 528;
            tile[i*33 + j] = im[sympad(rr)*512 + sympad(cc)];
        }
        __syncthreads();
        int r = r0 + t;
        if (r > 510) return;
        float rowv[33];
        float acc[17];
        #pragma unroll
        for (int c = 0; c < 17; c++) acc[c] = 0.f;
        for (int u = 0; u < 17; u++) {
            #pragma unroll
            for (int j = 0; j < 33; j++) rowv[j] = tile[(t + 16 - u)*33 + j];
            #pragma unroll
            for (int v = 0; v < 17; v++) {
                float s = psf_s[u*17 + v];
                #pragma unroll
                for (int c = 0; c < 17; c++)
                    acc[c] = fmaf(s, rowv[c - v + 16], acc[c]);
            }
        }
        #pragma unroll
        for (int c = 0; c < 17; c++) bb[(size_t)r*528 + basec + c] = acc[c];
    }
}

// ---------------- big passes --------------------------------------------------
// P1E: symmetric-pad + inline edgetaper mix (blur from band buffer), pack two
// real rows, one forward FFT, Hermitian unpack -> bufA.
__global__ void __launch_bounds__(256, 6) k_p1e(const float* image) {
    __shared__ float2 tw[TWSZ];
    __shared__ float2 sA[LPB][LSTR];
    int tx = threadIdx.x, ty = threadIdx.y;
    int tid = ty*64 + tx;
    for (int i = tid; i < TWSZ; i += 256) tw[i] = g_tw[i];
    int line = blockIdx.x*LPB + ty;           // pair index
    int img = line / 264, q = line % 264;
    int r1 = 2*q, r2 = 2*q + 1;
    int b = img / 3;
    const float* ar0 = g_r0 + b*17;
    const float* ar1 = g_r1 + b*17;
    float inv0 = 1.f / ar0[0];
    float inv1 = 1.f / ar1[0];
    float b01 = betaraw(r1, ar0) * inv0;
    float b02 = betaraw(r2, ar0) * inv0;
    const float* src1 = image + ((size_t)img*512 + sympad(r1))*512;
    const float* src2 = image + ((size_t)img*512 + sympad(r2))*512;
    const float* bb1 = (const float*)g_bufB + ((size_t)img*528 + r1)*528;
    const float* bb2 = (const float*)g_bufB + ((size_t)img*528 + r2)*528;
    for (int j = tx; j < NP; j += 64) {
        float b1j = betaraw(j, ar1) * inv1;
        float a1 = (1.f - b01) * (1.f - b1j);
        float a2 = (1.f - b02) * (1.f - b1j);
        int sj = sympad(j);
        float x1 = src1[sj], x2 = src2[sj];
        if (a1 != 1.f) x1 = a1 * x1 + (1.f - a1) * bb1[j];
        if (a2 != 1.f) x2 = a2 * x2 + (1.f - a2) * bb2[j];
        sA[ty][j] = make_float2(x1, x2);
    }
    fft528<-1>(sA[ty], tw, tx);
    float2* d1 = g_bufA + (size_t)img*NP*NPH + (size_t)r1*NPH;
    float2* d2 = g_bufA + (size_t)img*NP*NPH + (size_t)r2*NPH;
    for (int k = tx; k < 265; k += 64) {
        float2 Zk = sA[ty][k];
        float2 Zm = sA[ty][(NP - k) % NP];
        d1[k] = make_float2(0.5f*(Zk.x + Zm.x), 0.5f*(Zk.y - Zm.y));
        d2[k] = make_float2(0.5f*(Zk.y + Zm.y), 0.5f*(Zm.x - Zk.x));
    }
}

// Column pass over half-width columns: col FFT, multiply spectrum M,
// col IFFT (x 1/528). bufA -> bufB. float4 global I/O.
__global__ void __launch_bounds__(256, 6) k_colpass() {
    __shared__ float2 tw[TWSZ];
    __shared__ float2 sA[LPB][LSTR];
    int tx = threadIdx.x, ty = threadIdx.y;
    int tid = ty*64 + tx;
    for (int i = tid; i < TWSZ; i += 256) tw[i] = g_tw[i];
    int img = blockIdx.y;
    int c0  = blockIdx.x * LPB;
    int b   = img / 3;
    const float4* in4  = (const float4*)(g_bufA + (size_t)img * NP * NPH);
    float4*       out4 = (float4*)(g_bufB + (size_t)img * NP * NPH);
    const float4* spec4 = (const float4*)(g_M + (size_t)b * NP * NPH);
    for (int e = tid; e < NP*2; e += 256) {
        int r = e >> 1, p = e & 1;
        float4 v = in4[(r*NPH + c0)/2 + p];
        sA[2*p  ][r] = make_float2(v.x, v.y);
        sA[2*p+1][r] = make_float2(v.z, v.w);
    }
    fft528<-1>(sA[ty], tw, tx);
    for (int e = tid; e < NP*2; e += 256) {
        int r = e >> 1, p = e & 1;
        float4 s = spec4[(r*NPH + c0)/2 + p];
        float2 v0 = sA[2*p][r], v1 = sA[2*p+1][r];
        sA[2*p  ][r] = make_float2(v0.x*s.x - v0.y*s.y, v0.x*s.y + v0.y*s.x);
        sA[2*p+1][r] = make_float2(v1.x*s.z - v1.y*s.w, v1.x*s.w + v1.y*s.z);
    }
    fft528<1>(sA[ty], tw, tx);
    const float inv = 1.f / NP;
    for (int e = tid; e < NP*2; e += 256) {
        int r = e >> 1, p = e & 1;
        float2 v0 = sA[2*p][r], v1 = sA[2*p+1][r];
        out4[(r*NPH + c0)/2 + p] = make_float4(v0.x*inv, v0.y*inv, v1.x*inv, v1.y*inv);
    }
}

// P5: two Hermitian half-rows -> packed IFFT, crop, write both output rows.
__global__ void __launch_bounds__(256, 6) k_p5(float* outp) {
    __shared__ float2 tw[TWSZ];
    __shared__ float2 sA[LPB][LSTR];
    int tx = threadIdx.x, ty = threadIdx.y;
    int tid = ty*64 + tx;
    for (int i = tid; i < TWSZ; i += 256) tw[i] = g_tw[i];
    int line = blockIdx.x*LPB + ty;
    int img = line / 256, q = line % 256;
    int o1 = 2*q, o2 = 2*q + 1;
    int r1 = o1 + 8, r2 = o2 + 8;
    const float2* i1 = g_bufB + (size_t)img*NP*NPH + (size_t)r1*NPH;
    const float2* i2 = g_bufB + (size_t)img*NP*NPH + (size_t)r2*NPH;
    for (int m = tx; m < 265; m += 64) {
        float2 B1 = i1[m], B2 = i2[m];
        sA[ty][m] = make_float2(B1.x - B2.y, B1.y + B2.x);
        if (m >= 1 && m <= 263)
            sA[ty][NP - m] = make_float2(B1.x + B2.y, B2.x - B1.y);
    }
    fft528<1>(sA[ty], tw, tx);
    const float inv = 1.f / NP;
    float* d1 = outp + ((size_t)img*512 + o1)*512;
    float* d2 = outp + ((size_t)img*512 + o2)*512;
    for (int j = 8 + tx; j < 520; j += 64) {
        float2 z = sA[ty][j];
        d1[j - 8] = z.x * inv;
        d2[j - 8] = z.y * inv;
    }
}

// ---------------- launch ------------------------------------------------------
extern "C" void kernel_launch(void* const* d_in, const int* in_sizes, int n_in,
                              void* d_out, int out_size) {
    const float* image  = (const float*)d_in[0];
    const float* blurK  = (const float*)d_in[1];
    // d_in[2] = stdn (unused by the reference forward pass)
    const float* wcw    = (const float*)d_in[3];
    const float* wscale = (const float*)d_in[4];
    const float* alpha  = (const float*)d_in[5];
    const float* wts    = (const float*)d_in[6];
    float* outp = (float*)d_out;

    k_band<<<dim3(17, 2, NIMG), 64>>>(image, blurK);
    k_prep<<<1, NP>>>(wcw, wscale, alpha, wts, blurK);
    k_spec<<<dim3(33, NB), NPH>>>(blurK);

    dim3 blk(64, LPB);
    k_p1e<<<(NIMG*264)/LPB, blk>>>(image);
    k_colpass<<<dim3(67, NIMG), blk>>>();
    k_p5<<<(NIMG*256)/LPB, blk>>>(outp);
}